// round 13
// baseline (speedup 1.0000x reference)
#include <cuda_runtime.h>
#include <math.h>

// ---------------- problem constants ----------------
#define HH 480
#define WW2 480
#define HXW (HH*WW2)            // 230400
#define BATCH 8
#define NPIX (BATCH*HXW)        // 1843200
#define NCH 19
#define GRID_P 160
#define NPATCH (BATCH*GRID_P*GRID_P)   // 204800
#define PPB 32                  // patches per block (1 token per thread)
#define TPB (PPB*9)             // 288 threads
#define KSTR 18                 // smem row stride (floats)

typedef unsigned long long ull;

// ---------------- f32x2 helpers ----------------
__device__ __forceinline__ ull pk2(float a, float b) {
    ull r; asm("mov.b64 %0, {%1,%2};" : "=l"(r) : "f"(a), "f"(b)); return r;
}
__device__ __forceinline__ ull dup2(float a) {
    ull r; asm("mov.b64 %0, {%1,%1};" : "=l"(r) : "f"(a)); return r;
}
__device__ __forceinline__ void upk2(ull v, float& a, float& b) {
    asm("mov.b64 {%0,%1}, %2;" : "=f"(a), "=f"(b) : "l"(v));
}
__device__ __forceinline__ ull fma2(ull a, ull b, ull c) {
    ull d; asm("fma.rn.f32x2 %0, %1, %2, %3;" : "=l"(d) : "l"(a), "l"(b), "l"(c)); return d;
}

// ---------------- device scratch ----------------
__device__ float  g_semprob[NPIX];
__device__ double g_acc[BATCH][4];
__device__ double g_gate_acc[3];
__device__ float4 g_norm[BATCH];

// Broadcast weights on the CONSTANT port (separate from L1/smem writeback).
// Layout (ull units, 8B each):
//   [0:128)   eg_w1   [128:256) eg_w2
//   [256:384) es_w1   [384:512) es_w2
//   [512:640) ef_w1   [640:768) ef_w2
//   [768:896) out_w
//   [896:920) qa  [920:944) qb  [944:968) qc  [968:992) qd   (rank-2 qkv fold)
__constant__ ull c_w64[992];
#define CB_EG1 0
#define CB_EG2 128
#define CB_ES1 256
#define CB_ES2 384
#define CB_EF1 512
#define CB_EF2 640
#define CB_OUTW 768
#define CB_QA 896
#define CB_QB 920
#define CB_QC 944
#define CB_QD 968

// ---------------- packed weights (smem-resident part) ----------------
// NOTE: qa..qd remain at the head of SW — pack_kernel writes them here, then
// the launcher D2D-copies them into c_w64 (stream-ordered after pack_kernel).
struct SW {
    float qa[48]; float qb[48]; float qc[48]; float qd[48];
    float out_b[16];
    float Ag[16]; float Bg[16]; float Cg[16];
    float As[16]; float Bs[16]; float Cs[16];
    float Af[16]; float Bf[16]; float Cf[16];
    float b2g[16]; float b2s[16]; float b2f[16];
    float gw1t[768]; float gb1[16]; float gw2[48]; float gb2[4];
    float pw[16];   float pb[4];
    float dpw[16]; float dpb[16]; float spw[16]; float spb[16];
    float xga[16]; float xgb[16]; float xgc[16];
    float mst[8];          // M_aa, M_ab, M_bb, M_ac, M_bc, M_cc, pad, pad
    float n1g[16]; float n1b[16]; float n2g[16]; float n2b[16];
};
#define NWFLOATS ((int)(sizeof(SW)/4))
__device__ float g_wblob[sizeof(SW)/4];

struct Ptrs { const float* p[32]; };

// dynamic smem layout
#define SW_BYTES ((int)sizeof(SW))
#define SK_OFF   SW_BYTES
#define SK_BYTES (TPB*KSTR*4)                 // 20736
#define SV_OFF   (SK_OFF + SK_BYTES)
// overlays (valid after attention completes):
#define SX_OFF    SK_OFF                      // x rows [tid][KSTR]
#define SSTAT_OFF SV_OFF                      // [32][48] gate stats
#define SHID_OFF  (SSTAT_OFF + 32*48*4)       // [32][16] gate hidden
#define SGATE_OFF (SV_OFF + SK_BYTES)
#define SMEM_TOTAL (SGATE_OFF + 32)

// ---------------- pack weights + precompute folds ----------------
__global__ void pack_kernel(Ptrs in) {
    SW* w = (SW*)g_wblob;
    const int tid = threadIdx.x, nt = blockDim.x;
#define CP(dst, idx, n) for (int i = tid; i < (n); i += nt) (dst)[i] = in.p[idx][i];
    CP(w->out_b, 9, 16)
    CP(w->b2g, 15, 16)   CP(w->b2s, 19, 16)  CP(w->b2f, 23, 16)
    CP(w->gb1, 27, 16)   CP(w->gw2, 28, 48)  CP(w->pw, 30, 16)
    CP(w->dpw, 2, 16) CP(w->dpb, 3, 16) CP(w->spw, 4, 16) CP(w->spb, 5, 16)
    CP(w->n1g, 10, 16) CP(w->n1b, 11, 16) CP(w->n2g, 24, 16) CP(w->n2b, 25, 16)
#undef CP
    for (int i = tid; i < 768; i += nt) {         // g_w1 [48,16] -> gw1t [16][48]
        int r = i / 48, s = i - r * 48;
        w->gw1t[i] = in.p[26][s * 16 + r];
    }
    // means of embed basis vectors
    double abar = 0, bbar = 0, cbar = 0;
    for (int k = 0; k < 16; k++) {
        abar += in.p[2][k]; bbar += in.p[4][k];
        cbar += (double)in.p[3][k] + in.p[5][k];
    }
    abar /= 16.0; bbar /= 16.0; cbar /= 16.0;

    // qa..qd (48 outputs)
    if (tid < 48) {
        const int o = tid;
        double pa = 0, pb = 0, pc = 0, pd = in.p[7][o];
        for (int j = 0; j < 16; j++) {
            const double a0 = in.p[2][j] - abar;
            const double b0 = in.p[4][j] - bbar;
            const double c0 = ((double)in.p[3][j] + in.p[5][j]) - cbar;
            const double g = in.p[10][j];
            const double wv = in.p[6][j * 48 + o];
            pa += a0 * g * wv; pb += b0 * g * wv; pc += c0 * g * wv;
            pd += (double)in.p[11][j] * wv;
        }
        w->qa[o] = (float)pa; w->qb[o] = (float)pb;
        w->qc[o] = (float)pc; w->qd[o] = (float)pd;
    }
    // xga/xgb/xgc (16 each)
    if (tid >= 64 && tid < 80) {
        const int j = tid - 64;
        const double a0 = in.p[2][j] - abar;
        const double b0 = in.p[4][j] - bbar;
        const double c0 = ((double)in.p[3][j] + in.p[5][j]) - cbar;
        const double g = in.p[10][j];
        w->xga[j] = (float)(a0 * g); w->xgb[j] = (float)(b0 * g); w->xgc[j] = (float)(c0 * g);
    }
    // variance moments
    if (tid == 96) {
        double maa = 0, mab = 0, mbb = 0, mac = 0, mbc = 0, mcc = 0;
        for (int j = 0; j < 16; j++) {
            const double a0 = in.p[2][j] - abar;
            const double b0 = in.p[4][j] - bbar;
            const double c0 = ((double)in.p[3][j] + in.p[5][j]) - cbar;
            maa += a0*a0; mab += a0*b0; mbb += b0*b0;
            mac += a0*c0; mbc += b0*c0; mcc += c0*c0;
        }
        w->mst[0] = (float)(maa/16.0); w->mst[1] = (float)(mab/16.0);
        w->mst[2] = (float)(mbb/16.0); w->mst[3] = (float)(mac/16.0);
        w->mst[4] = (float)(mbc/16.0); w->mst[5] = (float)(mcc/16.0);
        w->mst[6] = 0.f; w->mst[7] = 0.f;
    }
    if (tid >= 128 && tid < 144) {                // expert rank-1 folds
        const int j = tid - 128;
        float ag = 0, cg = 0, bs = 0, cs = 0, af = 0, bf = 0, cf = 0;
        for (int k = 0; k < 16; k++) {
            const float eg = in.p[12][k*16 + j], es = in.p[16][k*16 + j], ef = in.p[20][k*16 + j];
            const float dpwk = in.p[2][k], dpbk = in.p[3][k];
            const float spwk = in.p[4][k], spbk = in.p[5][k];
            ag += dpwk * eg;  cg += dpbk * eg;
            bs += spwk * es;  cs += spbk * es;
            af += dpwk * ef;  bf += spwk * ef;
            cf += (dpbk + spbk) * ef;
        }
        w->Ag[j] = ag; w->Bg[j] = 0.f; w->Cg[j] = cg + in.p[13][j];
        w->As[j] = 0.f; w->Bs[j] = bs; w->Cs[j] = cs + in.p[17][j];
        w->Af[j] = af; w->Bf[j] = bf; w->Cf[j] = cf + in.p[21][j];
    }
    if (tid < 3) w->gb2[tid] = in.p[29][tid];
    if (tid == 3) w->gb2[3] = 0.f;
    if (tid == 0) w->pb[0] = in.p[31][0];
    if (tid < BATCH*4) ((double*)g_acc)[tid] = 0.0;
    if (tid < 3) g_gate_acc[tid] = 0.0;
}

// ---------------- stage 1: sem_prob + per-sample stats (float4) ----------------
__global__ void semprob_kernel(const float* __restrict__ sem,
                               const float* __restrict__ depth) {
    const int q = blockIdx.x * 256 + threadIdx.x;
    const int p4 = q * 4;
    const int b = p4 / HXW;
    const int ip = p4 - b * HXW;
    const float4* base = (const float4*)(sem + (long)b * NCH * HXW + ip);
    float4 v[NCH];
#pragma unroll
    for (int c = 0; c < NCH; c++) v[c] = __ldg(base + (long)c * (HXW/4));
    float4 mx = v[0];
#pragma unroll
    for (int c = 1; c < NCH; c++) {
        mx.x = fmaxf(mx.x, v[c].x); mx.y = fmaxf(mx.y, v[c].y);
        mx.z = fmaxf(mx.z, v[c].z); mx.w = fmaxf(mx.w, v[c].w);
    }
    float4 sum = make_float4(0.f, 0.f, 0.f, 0.f);
#pragma unroll
    for (int c = 0; c < NCH; c++) {
        sum.x += __expf(v[c].x - mx.x); sum.y += __expf(v[c].y - mx.y);
        sum.z += __expf(v[c].z - mx.z); sum.w += __expf(v[c].w - mx.w);
    }
    float4 prob;
    prob.x = __fdividef(1.0f, sum.x); prob.y = __fdividef(1.0f, sum.y);
    prob.z = __fdividef(1.0f, sum.z); prob.w = __fdividef(1.0f, sum.w);
    ((float4*)g_semprob)[q] = prob;
    const float4 d = __ldg((const float4*)depth + q);

    double rd  = (double)d.x + (double)d.y + (double)d.z + (double)d.w;
    double rd2 = (double)d.x*d.x + (double)d.y*d.y + (double)d.z*d.z + (double)d.w*d.w;
    double rs  = (double)prob.x + (double)prob.y + (double)prob.z + (double)prob.w;
    double rs2 = (double)prob.x*prob.x + (double)prob.y*prob.y
               + (double)prob.z*prob.z + (double)prob.w*prob.w;
#pragma unroll
    for (int off = 16; off > 0; off >>= 1) {
        rd  += __shfl_down_sync(0xffffffffu, rd,  off);
        rd2 += __shfl_down_sync(0xffffffffu, rd2, off);
        rs  += __shfl_down_sync(0xffffffffu, rs,  off);
        rs2 += __shfl_down_sync(0xffffffffu, rs2, off);
    }
    __shared__ double sp[8][4];
    const int lane = threadIdx.x & 31, wid = threadIdx.x >> 5;
    if (lane == 0) { sp[wid][0] = rd; sp[wid][1] = rd2; sp[wid][2] = rs; sp[wid][3] = rs2; }
    __syncthreads();
    if (threadIdx.x == 0) {
        double a0 = 0, a1 = 0, a2 = 0, a3 = 0;
        for (int i = 0; i < 8; i++) { a0 += sp[i][0]; a1 += sp[i][1]; a2 += sp[i][2]; a3 += sp[i][3]; }
        atomicAdd(&g_acc[b][0], a0); atomicAdd(&g_acc[b][1], a1);
        atomicAdd(&g_acc[b][2], a2); atomicAdd(&g_acc[b][3], a3);
    }
}

__global__ void finalize_kernel() {
    const int b = threadIdx.x;
    if (b < BATCH) {
        const double n = (double)HXW;
        double md = g_acc[b][0] / n;
        double vd = (g_acc[b][1] - n * md * md) / (n - 1.0);
        double ms = g_acc[b][2] / n;
        double vs = (g_acc[b][3] - n * ms * ms) / (n - 1.0);
        g_norm[b] = make_float4((float)md, (float)(1.0 / (sqrt(vd) + 1e-6)),
                                (float)ms, (float)(1.0 / (sqrt(vs) + 1e-6)));
    }
}

// ---------------- stage 2 helpers ----------------
__device__ __forceinline__ void ln16(float* x, const float* g, const float* b) {
    float m = 0.f;
#pragma unroll
    for (int j = 0; j < 16; j++) m += x[j];
    m *= 0.0625f;
    float v = 0.f;
#pragma unroll
    for (int j = 0; j < 16; j++) { float d = x[j] - m; v = fmaf(d, d, v); }
    v *= 0.0625f;
    const float r = rsqrtf(v + 1e-5f);
#pragma unroll
    for (int j = 0; j < 16; j++) x[j] = (x[j] - m) * r * g[j] + b[j];
}

// branchless gelu: A&S 7.1.26 erf (|eps| <= 1.5e-7)
__device__ __forceinline__ float gelu_fast(float x) {
    const float u = 0.70710678118654752f * x;
    const float a = fabsf(u);
    const float t = __fdividef(1.0f, fmaf(0.3275911f, a, 1.0f));
    float p =              1.061405429f;
    p = fmaf(p, t, -1.453152027f);
    p = fmaf(p, t,  1.421413741f);
    p = fmaf(p, t, -0.284496736f);
    p = fmaf(p, t,  0.254829592f);
    p = p * t;
    const float e = __expf(-u * u);
    float erf_u = 1.0f - p * e;
    erf_u = copysignf(erf_u, u);
    return 0.5f * x * (1.0f + erf_u);
}

// ---------------- stage 2: per-patch transformer/MoE ----------------
__global__ void __launch_bounds__(TPB, 2)
moe_kernel(const float* __restrict__ depth, float* __restrict__ out) {
    extern __shared__ __align__(16) unsigned char dsm[];
    SW& w = *(SW*)dsm;
    float* s_k = (float*)(dsm + SK_OFF);      // [TPB][KSTR]
    float* s_v = (float*)(dsm + SV_OFF);      // [TPB][KSTR]
    float* s_x = (float*)(dsm + SX_OFF);      // overlay on s_k
    float* s_st = (float*)(dsm + SSTAT_OFF);  // [32][48] overlay on s_v
    float* s_hid = (float*)(dsm + SHID_OFF);  // [32][16]
    double* s_gate = (double*)(dsm + SGATE_OFF);

    const int tid = threadIdx.x;
    for (int i = tid; i < NWFLOATS; i += TPB) ((float*)&w)[i] = g_wblob[i];
    if (tid < 3) s_gate[tid] = 0.0;
    __syncthreads();                                         // S0

    const int pl = tid / 9;
    const int t = tid - pl * 9;
    const int P = blockIdx.x * PPB + pl;
    const int b = P / (GRID_P * GRID_P);
    const int rem = P - b * (GRID_P * GRID_P);
    const int hh = rem / GRID_P, ww = rem - hh * GRID_P;
    const int py = hh * 3 + t / 3, px = ww * 3 + (t % 3);
    const int pix = (b * HH + py) * WW2 + px;
    const int pb = tid - t;                                  // first thread of patch

    const float4 nm = g_norm[b];
    const float dn = (depth[pix] - nm.x) * nm.y;
    const float sn = (g_semprob[pix] - nm.z) * nm.w;

    // ---- collapsed embed+LN1: r = rsqrt(var+eps), var = quadratic in (dn,sn) ----
    float rr_s;
    {
        const float var = w.mst[0]*dn*dn + 2.f*w.mst[1]*dn*sn + w.mst[2]*sn*sn
                        + 2.f*w.mst[3]*dn + 2.f*w.mst[4]*sn + w.mst[5];
        rr_s = rsqrtf(var + 1e-5f);
    }
    const ull dnd = dup2(dn), snd = dup2(sn), rr = dup2(rr_s);

    // x = r*(dn*xga + sn*xgb + xgc) + n1b
    float x[16];
    {
        const ull *A = (const ull*)w.xga, *B = (const ull*)w.xgb,
                  *C = (const ull*)w.xgc, *N = (const ull*)w.n1b;
#pragma unroll
        for (int p = 0; p < 8; p++) {
            const ull v = fma2(rr, fma2(dnd, A[p], fma2(snd, B[p], C[p])), N[p]);
            upk2(v, x[2*p], x[2*p+1]);
        }
    }

    // ---- collapsed qkv (constant port): qkv = r*(dn*qa + sn*qb + qc) + qd ----
    ull aq[8];
    {
        ull* krow = (ull*)&s_k[tid * KSTR];
        ull* vrow = (ull*)&s_v[tid * KSTR];
#pragma unroll
        for (int p = 0; p < 8; p++)
            aq[p] = fma2(rr, fma2(dnd, c_w64[CB_QA + p],
                          fma2(snd, c_w64[CB_QB + p], c_w64[CB_QC + p])), c_w64[CB_QD + p]);
#pragma unroll
        for (int p = 0; p < 8; p++)
            krow[p] = fma2(rr, fma2(dnd, c_w64[CB_QA + 8 + p],
                          fma2(snd, c_w64[CB_QB + 8 + p], c_w64[CB_QC + 8 + p])), c_w64[CB_QD + 8 + p]);
#pragma unroll
        for (int p = 0; p < 8; p++)
            vrow[p] = fma2(rr, fma2(dnd, c_w64[CB_QA + 16 + p],
                          fma2(snd, c_w64[CB_QB + 16 + p], c_w64[CB_QC + 16 + p])), c_w64[CB_QD + 16 + p]);
    }
    __syncthreads();                                         // S1

    // ---- attention ----
    float ao[16];
#pragma unroll
    for (int h = 0; h < 2; h++) {
        float sc[9]; float mx = -1e30f;
#pragma unroll
        for (int tt = 0; tt < 9; tt++) {
            const ull* kr = (const ull*)&s_k[(pb + tt) * KSTR];
            ull acc = 0ull;
#pragma unroll
            for (int p = 0; p < 4; p++) acc = fma2(aq[h*4 + p], kr[h*4 + p], acc);
            float a0, a1; upk2(acc, a0, a1);
            const float s = (a0 + a1) * 0.35355339059327373f;
            sc[tt] = s; mx = fmaxf(mx, s);
        }
        float sum = 0.f;
#pragma unroll
        for (int tt = 0; tt < 9; tt++) { sc[tt] = __expf(sc[tt] - mx); sum += sc[tt]; }
        const float inv = __fdividef(1.0f, sum);
        ull vacc[4] = {0ull, 0ull, 0ull, 0ull};
#pragma unroll
        for (int tt = 0; tt < 9; tt++) {
            const ull s2 = dup2(sc[tt]);
            const ull* vr = (const ull*)&s_v[(pb + tt) * KSTR];
#pragma unroll
            for (int p = 0; p < 4; p++) vacc[p] = fma2(s2, vr[h*4 + p], vacc[p]);
        }
#pragma unroll
        for (int p = 0; p < 4; p++) {
            float a0, a1; upk2(vacc[p], a0, a1);
            ao[h*8 + 2*p] = a0 * inv; ao[h*8 + 2*p + 1] = a1 * inv;
        }
    }
    // out projection (constant port) + residual + LN (n1 reused)
    {
        ull acc[8];
        const ull* bp = (const ull*)w.out_b;
#pragma unroll
        for (int p = 0; p < 8; p++) acc[p] = bp[p];
#pragma unroll
        for (int k = 0; k < 16; k++) {
            const ull v0 = dup2(ao[k]);
#pragma unroll
            for (int p = 0; p < 8; p++) acc[p] = fma2(v0, c_w64[CB_OUTW + k*8 + p], acc[p]);
        }
#pragma unroll
        for (int p = 0; p < 8; p++) {
            float f0, f1; upk2(acc[p], f0, f1);
            x[2*p] += f0; x[2*p+1] += f1;
        }
    }
    ln16(x, w.n1g, w.n1b);

    __syncthreads();                                         // S2: attn reads done
#pragma unroll
    for (int j = 0; j < 16; j++) s_x[tid * KSTR + j] = x[j];
    __syncthreads();                                         // S3

    // ---- gate: cooperative stats (each thread 1-2 channels) ----
#pragma unroll
    for (int cc = 0; cc < 2; cc++) {
        const int j = (cc == 0) ? t : (9 + t);
        if (cc == 0 || t < 7) {
            float vals[9]; float m = 0.f, mxv = -1e30f;
#pragma unroll
            for (int tt = 0; tt < 9; tt++) {
                const float v = s_x[(pb + tt) * KSTR + j];
                vals[tt] = v; m += v; mxv = fmaxf(mxv, v);
            }
            m *= (1.0f / 9.0f);
            float var = 0.f;
#pragma unroll
            for (int tt = 0; tt < 9; tt++) { const float d = vals[tt] - m; var = fmaf(d, d, var); }
            const float sd = sqrtf(var * 0.125f);            // ddof=1
            float* st = &s_st[pl * 48];
            st[j] = m; st[16 + j] = mxv; st[32 + j] = sd;
        }
    }
    __syncthreads();                                         // S4

    // hid: thread t<8 computes outputs t and 8+t
    if (t < 8) {
        const ull* stp = (const ull*)&s_st[pl * 48];
#pragma unroll
        for (int cc = 0; cc < 2; cc++) {
            const int i = (cc == 0) ? t : (8 + t);
            const ull* wr = (const ull*)&w.gw1t[i * 48];
            ull acc = 0ull;
#pragma unroll
            for (int p = 0; p < 24; p++) acc = fma2(stp[p], wr[p], acc);
            float a0, a1; upk2(acc, a0, a1);
            s_hid[pl * 16 + i] = gelu_fast(a0 + a1 + w.gb1[i]);
        }
    }
    __syncthreads();                                         // S5

    // logits + softmax (redundant per thread, cheap)
    float g0, g1, g2;
    {
        float lg0 = w.gb2[0], lg1 = w.gb2[1], lg2 = w.gb2[2];
        const float* hv = &s_hid[pl * 16];
#pragma unroll
        for (int i = 0; i < 16; i++) {
            const float h = hv[i];
            lg0 = fmaf(h, w.gw2[i*3 + 0], lg0);
            lg1 = fmaf(h, w.gw2[i*3 + 1], lg1);
            lg2 = fmaf(h, w.gw2[i*3 + 2], lg2);
        }
        const float mxl = fmaxf(lg0, fmaxf(lg1, lg2));
        const float e0 = __expf(lg0 - mxl), e1 = __expf(lg1 - mxl), e2 = __expf(lg2 - mxl);
        const float inv = __fdividef(1.0f, e0 + e1 + e2);
        g0 = e0 * inv; g1 = e1 * inv; g2 = e2 * inv;
    }
    if (t == 0) {
        atomicAdd(&s_gate[0], (double)g0);
        atomicAdd(&s_gate[1], (double)g1);
        atomicAdd(&s_gate[2], (double)g2);
    }

    // ---- experts: all W1/W2 on the constant port; vectors on smem port ----
    ull moe[8];
    {
        const ull g0d = dup2(g0), g1d = dup2(g1), g2d = dup2(g2);
        const ull *bg = (const ull*)w.b2g, *bs = (const ull*)w.b2s, *bf = (const ull*)w.b2f;
#pragma unroll
        for (int p = 0; p < 8; p++)
            moe[p] = fma2(g0d, bg[p], fma2(g1d, bs[p], fma2(g2d, bf[p], 0ull)));
    }

#define EXPERT_C(B1, B2, AA, BB, CC, GE) {                                \
        ull h_[8];                                                        \
        {                                                                 \
            const ull *Ap = (const ull*)(AA), *Bp = (const ull*)(BB),     \
                      *Cp = (const ull*)(CC);                             \
            _Pragma("unroll") for (int p = 0; p < 8; p++)                 \
                h_[p] = fma2(dnd, Ap[p], fma2(snd, Bp[p], Cp[p]));        \
        }                                                                 \
        _Pragma("unroll") for (int k = 0; k < 16; k++) {                  \
            const ull xv = dup2(x[k]);                                    \
            _Pragma("unroll") for (int p = 0; p < 8; p++)                 \
                h_[p] = fma2(xv, c_w64[(B1) + k*8 + p], h_[p]);           \
        }                                                                 \
        float hf[16];                                                     \
        _Pragma("unroll") for (int p = 0; p < 8; p++) {                   \
            float a0, a1; upk2(h_[p], a0, a1);                            \
            hf[2*p] = gelu_fast(a0) * (GE); hf[2*p+1] = gelu_fast(a1) * (GE); \
        }                                                                 \
        _Pragma("unroll") for (int k = 0; k < 16; k++) {                  \
            const ull v0 = dup2(hf[k]);                                   \
            _Pragma("unroll") for (int p = 0; p < 8; p++)                 \
                moe[p] = fma2(v0, c_w64[(B2) + k*8 + p], moe[p]);         \
        }                                                                 \
    }

    EXPERT_C(CB_EG1, CB_EG2, w.Ag, w.Bg, w.Cg, g0)
    EXPERT_C(CB_ES1, CB_ES2, w.As, w.Bs, w.Cs, g1)
    EXPERT_C(CB_EF1, CB_EF2, w.Af, w.Bf, w.Cf, g2)
#undef EXPERT_C

    // ---- final: residual folds + LN + project + sigmoid ----
    {
        const ull two = dup2(2.0f);
        const ull gdp = dup2(g0 + g2);
        const ull gsp = dup2(g1 + g2);
        const ull *dw = (const ull*)w.dpw, *db = (const ull*)w.dpb;
        const ull *sw = (const ull*)w.spw, *sb = (const ull*)w.spb;
        float mf[16];
#pragma unroll
        for (int p = 0; p < 8; p++) {
            ull v = fma2(two, pk2(x[2*p], x[2*p+1]), moe[p]);
            const ull dpf = fma2(dnd, dw[p], db[p]);
            const ull spf = fma2(snd, sw[p], sb[p]);
            v = fma2(gdp, dpf, v);
            v = fma2(gsp, spf, v);
            upk2(v, mf[2*p], mf[2*p+1]);
        }
        ln16(mf, w.n2g, w.n2b);
        float z = w.pb[0];
#pragma unroll
        for (int j = 0; j < 16; j++) z = fmaf(mf[j], w.pw[j], z);
        out[pix] = __fdividef(1.0f, 1.0f + __expf(-z));
    }

    __syncthreads();                                         // S6
    if (tid < 3) atomicAdd(&g_gate_acc[tid], s_gate[tid]);
}

__global__ void tail_kernel(float* __restrict__ out) {
    if (threadIdx.x < 3)
        out[NPIX + threadIdx.x] = (float)(g_gate_acc[threadIdx.x] / (double)NPATCH);
}

// ---------------- launch ----------------
extern "C" void kernel_launch(void* const* d_in, const int* in_sizes, int n_in,
                              void* d_out, int out_size) {
    Ptrs ptrs;
    for (int i = 0; i < 32; i++) ptrs.p[i] = (const float*)d_in[i];
    const float* depth = (const float*)d_in[0];
    const float* sem   = (const float*)d_in[1];
    float* out = (float*)d_out;

    cudaFuncSetAttribute(moe_kernel, cudaFuncAttributeMaxDynamicSharedMemorySize, SMEM_TOTAL);

    // populate constant weights from inputs (graph-capturable async D2D)
    void* caddr = nullptr;
    cudaGetSymbolAddress(&caddr, c_w64);
    cudaMemcpyAsync((char*)caddr + CB_EG1*8,  d_in[12], 1024, cudaMemcpyDeviceToDevice);  // eg_w1
    cudaMemcpyAsync((char*)caddr + CB_EG2*8,  d_in[14], 1024, cudaMemcpyDeviceToDevice);  // eg_w2
    cudaMemcpyAsync((char*)caddr + CB_ES1*8,  d_in[16], 1024, cudaMemcpyDeviceToDevice);  // es_w1
    cudaMemcpyAsync((char*)caddr + CB_ES2*8,  d_in[18], 1024, cudaMemcpyDeviceToDevice);  // es_w2
    cudaMemcpyAsync((char*)caddr + CB_EF1*8,  d_in[20], 1024, cudaMemcpyDeviceToDevice);  // ef_w1
    cudaMemcpyAsync((char*)caddr + CB_EF2*8,  d_in[22], 1024, cudaMemcpyDeviceToDevice);  // ef_w2
    cudaMemcpyAsync((char*)caddr + CB_OUTW*8, d_in[8],  1024, cudaMemcpyDeviceToDevice);  // out_w

    pack_kernel<<<1, 256>>>(ptrs);

    // qa..qd live at the head of g_wblob (SW offset 0) after pack_kernel;
    // stream-ordered D2D copy into the constant bank.
    void* gaddr = nullptr;
    cudaGetSymbolAddress(&gaddr, g_wblob);
    cudaMemcpyAsync((char*)caddr + CB_QA*8, gaddr, 768, cudaMemcpyDeviceToDevice);

    semprob_kernel<<<NPIX / 4 / 256, 256>>>(sem, depth);
    finalize_kernel<<<1, 32>>>();
    moe_kernel<<<NPATCH / PPB, TPB, SMEM_TOTAL>>>(depth, out);
    tail_kernel<<<1, 32>>>(out);
}

// round 14
// speedup vs baseline: 1.0533x; 1.0533x over previous
#include <cuda_runtime.h>
#include <math.h>

// ---------------- problem constants ----------------
#define HH 480
#define WW2 480
#define HXW (HH*WW2)            // 230400
#define BATCH 8
#define NPIX (BATCH*HXW)        // 1843200
#define NCH 19
#define GRID_P 160
#define NPATCH (BATCH*GRID_P*GRID_P)   // 204800
#define PPB 32                  // patches per block (1 token per thread)
#define TPB (PPB*9)             // 288 threads
#define KSTR 18                 // smem row stride (floats)

typedef unsigned long long ull;

// ---------------- f32x2 helpers ----------------
__device__ __forceinline__ ull pk2(float a, float b) {
    ull r; asm("mov.b64 %0, {%1,%2};" : "=l"(r) : "f"(a), "f"(b)); return r;
}
__device__ __forceinline__ ull dup2(float a) {
    ull r; asm("mov.b64 %0, {%1,%1};" : "=l"(r) : "f"(a)); return r;
}
__device__ __forceinline__ void upk2(ull v, float& a, float& b) {
    asm("mov.b64 {%0,%1}, %2;" : "=f"(a), "=f"(b) : "l"(v));
}
__device__ __forceinline__ ull fma2(ull a, ull b, ull c) {
    ull d; asm("fma.rn.f32x2 %0, %1, %2, %3;" : "=l"(d) : "l"(a), "l"(b), "l"(c)); return d;
}

// ---------------- device scratch ----------------
__device__ float  g_semprob[NPIX];
__device__ double g_acc[BATCH][4];
__device__ double g_gate_acc[3];
__device__ float4 g_norm[BATCH];

// Broadcast weights on the CONSTANT port. Exactly 1024 ull = 8 KB (constant L1).
//   [0:128)   eg_w1   [128:256) eg_w2
//   [256:384) es_w1   [384:512) es_w2
//   [512:640) ef_w1   [640:768) ef_w2
//   [768:896) out_w
//   [896:920) qa  [920:944) qb  [944:968) qc  [968:992) qd
//   [992:1016) gw2 (48 floats)   [1016:1024) pw (16 floats)
__constant__ ull c_w64[1024];
#define CB_EG1 0
#define CB_EG2 128
#define CB_ES1 256
#define CB_ES2 384
#define CB_EF1 512
#define CB_EF2 640
#define CB_OUTW 768
#define CB_QA 896
#define CB_QB 920
#define CB_QC 944
#define CB_QD 968
#define CB_GW2 992
#define CB_PW 1016

// ---------------- packed weights (smem-resident part) ----------------
// qa..qd at head: pack_kernel writes them here; launcher D2D-copies to c_w64.
struct SW {
    float qa[48]; float qb[48]; float qc[48]; float qd[48];
    float out_b[16];
    float Ag[16]; float Bg[16]; float Cg[16];
    float As[16]; float Bs[16]; float Cs[16];
    float Af[16]; float Bf[16]; float Cf[16];
    float b2g[16]; float b2s[16]; float b2f[16];
    float gw1t[768]; float gb1[16]; float gb2[4];
    float pb[4];
    float dpw[16]; float dpb[16]; float spw[16]; float spb[16];
    float xga[16]; float xgb[16]; float xgc[16];
    float mst[8];          // M_aa, M_ab, M_bb, M_ac, M_bc, M_cc, pad, pad
    float n1g[16]; float n1b[16]; float n2g[16]; float n2b[16];
};
#define NWFLOATS ((int)(sizeof(SW)/4))
__device__ float g_wblob[sizeof(SW)/4];

struct Ptrs { const float* p[32]; };

// dynamic smem layout
#define SW_BYTES ((int)sizeof(SW))
#define SK_OFF   SW_BYTES
#define SK_BYTES (TPB*KSTR*4)                 // 20736
#define SV_OFF   (SK_OFF + SK_BYTES)
// overlays (valid after attention completes):
#define SX_OFF    SK_OFF                      // x rows [tid][KSTR]
#define SSTAT_OFF SV_OFF                      // [32][48] gate stats
#define SHID_OFF  (SSTAT_OFF + 32*48*4)       // [32][16] gate hidden
#define SGATE_OFF (SV_OFF + SK_BYTES)
#define SMEM_TOTAL (SGATE_OFF + 32)

// ---------------- pack weights + precompute folds ----------------
__global__ void pack_kernel(Ptrs in) {
    SW* w = (SW*)g_wblob;
    const int tid = threadIdx.x, nt = blockDim.x;
#define CP(dst, idx, n) for (int i = tid; i < (n); i += nt) (dst)[i] = in.p[idx][i];
    CP(w->out_b, 9, 16)
    CP(w->b2g, 15, 16)   CP(w->b2s, 19, 16)  CP(w->b2f, 23, 16)
    CP(w->gb1, 27, 16)
    CP(w->dpw, 2, 16) CP(w->dpb, 3, 16) CP(w->spw, 4, 16) CP(w->spb, 5, 16)
    CP(w->n1g, 10, 16) CP(w->n1b, 11, 16) CP(w->n2g, 24, 16) CP(w->n2b, 25, 16)
#undef CP
    for (int i = tid; i < 768; i += nt) {         // g_w1 [48,16] -> gw1t [16][48]
        int r = i / 48, s = i - r * 48;
        w->gw1t[i] = in.p[26][s * 16 + r];
    }
    // means of embed basis vectors
    double abar = 0, bbar = 0, cbar = 0;
    for (int k = 0; k < 16; k++) {
        abar += in.p[2][k]; bbar += in.p[4][k];
        cbar += (double)in.p[3][k] + in.p[5][k];
    }
    abar /= 16.0; bbar /= 16.0; cbar /= 16.0;

    // qa..qd (48 outputs)
    if (tid < 48) {
        const int o = tid;
        double pa = 0, pb = 0, pc = 0, pd = in.p[7][o];
        for (int j = 0; j < 16; j++) {
            const double a0 = in.p[2][j] - abar;
            const double b0 = in.p[4][j] - bbar;
            const double c0 = ((double)in.p[3][j] + in.p[5][j]) - cbar;
            const double g = in.p[10][j];
            const double wv = in.p[6][j * 48 + o];
            pa += a0 * g * wv; pb += b0 * g * wv; pc += c0 * g * wv;
            pd += (double)in.p[11][j] * wv;
        }
        w->qa[o] = (float)pa; w->qb[o] = (float)pb;
        w->qc[o] = (float)pc; w->qd[o] = (float)pd;
    }
    // xga/xgb/xgc (16 each)
    if (tid >= 64 && tid < 80) {
        const int j = tid - 64;
        const double a0 = in.p[2][j] - abar;
        const double b0 = in.p[4][j] - bbar;
        const double c0 = ((double)in.p[3][j] + in.p[5][j]) - cbar;
        const double g = in.p[10][j];
        w->xga[j] = (float)(a0 * g); w->xgb[j] = (float)(b0 * g); w->xgc[j] = (float)(c0 * g);
    }
    // variance moments
    if (tid == 96) {
        double maa = 0, mab = 0, mbb = 0, mac = 0, mbc = 0, mcc = 0;
        for (int j = 0; j < 16; j++) {
            const double a0 = in.p[2][j] - abar;
            const double b0 = in.p[4][j] - bbar;
            const double c0 = ((double)in.p[3][j] + in.p[5][j]) - cbar;
            maa += a0*a0; mab += a0*b0; mbb += b0*b0;
            mac += a0*c0; mbc += b0*c0; mcc += c0*c0;
        }
        w->mst[0] = (float)(maa/16.0); w->mst[1] = (float)(mab/16.0);
        w->mst[2] = (float)(mbb/16.0); w->mst[3] = (float)(mac/16.0);
        w->mst[4] = (float)(mbc/16.0); w->mst[5] = (float)(mcc/16.0);
        w->mst[6] = 0.f; w->mst[7] = 0.f;
    }
    if (tid >= 128 && tid < 144) {                // expert rank-1 folds
        const int j = tid - 128;
        float ag = 0, cg = 0, bs = 0, cs = 0, af = 0, bf = 0, cf = 0;
        for (int k = 0; k < 16; k++) {
            const float eg = in.p[12][k*16 + j], es = in.p[16][k*16 + j], ef = in.p[20][k*16 + j];
            const float dpwk = in.p[2][k], dpbk = in.p[3][k];
            const float spwk = in.p[4][k], spbk = in.p[5][k];
            ag += dpwk * eg;  cg += dpbk * eg;
            bs += spwk * es;  cs += spbk * es;
            af += dpwk * ef;  bf += spwk * ef;
            cf += (dpbk + spbk) * ef;
        }
        w->Ag[j] = ag; w->Bg[j] = 0.f; w->Cg[j] = cg + in.p[13][j];
        w->As[j] = 0.f; w->Bs[j] = bs; w->Cs[j] = cs + in.p[17][j];
        w->Af[j] = af; w->Bf[j] = bf; w->Cf[j] = cf + in.p[21][j];
    }
    if (tid < 3) w->gb2[tid] = in.p[29][tid];
    if (tid == 3) w->gb2[3] = 0.f;
    if (tid == 0) w->pb[0] = in.p[31][0];
    if (tid < BATCH*4) ((double*)g_acc)[tid] = 0.0;
    if (tid < 3) g_gate_acc[tid] = 0.0;
}

// ---------------- stage 1: sem_prob + per-sample stats (float4) ----------------
__global__ void semprob_kernel(const float* __restrict__ sem,
                               const float* __restrict__ depth) {
    const int q = blockIdx.x * 256 + threadIdx.x;
    const int p4 = q * 4;
    const int b = p4 / HXW;
    const int ip = p4 - b * HXW;
    const float4* base = (const float4*)(sem + (long)b * NCH * HXW + ip);
    float4 v[NCH];
#pragma unroll
    for (int c = 0; c < NCH; c++) v[c] = __ldg(base + (long)c * (HXW/4));
    float4 mx = v[0];
#pragma unroll
    for (int c = 1; c < NCH; c++) {
        mx.x = fmaxf(mx.x, v[c].x); mx.y = fmaxf(mx.y, v[c].y);
        mx.z = fmaxf(mx.z, v[c].z); mx.w = fmaxf(mx.w, v[c].w);
    }
    float4 sum = make_float4(0.f, 0.f, 0.f, 0.f);
#pragma unroll
    for (int c = 0; c < NCH; c++) {
        sum.x += __expf(v[c].x - mx.x); sum.y += __expf(v[c].y - mx.y);
        sum.z += __expf(v[c].z - mx.z); sum.w += __expf(v[c].w - mx.w);
    }
    float4 prob;
    prob.x = __fdividef(1.0f, sum.x); prob.y = __fdividef(1.0f, sum.y);
    prob.z = __fdividef(1.0f, sum.z); prob.w = __fdividef(1.0f, sum.w);
    ((float4*)g_semprob)[q] = prob;
    const float4 d = __ldg((const float4*)depth + q);

    double rd  = (double)d.x + (double)d.y + (double)d.z + (double)d.w;
    double rd2 = (double)d.x*d.x + (double)d.y*d.y + (double)d.z*d.z + (double)d.w*d.w;
    double rs  = (double)prob.x + (double)prob.y + (double)prob.z + (double)prob.w;
    double rs2 = (double)prob.x*prob.x + (double)prob.y*prob.y
               + (double)prob.z*prob.z + (double)prob.w*prob.w;
#pragma unroll
    for (int off = 16; off > 0; off >>= 1) {
        rd  += __shfl_down_sync(0xffffffffu, rd,  off);
        rd2 += __shfl_down_sync(0xffffffffu, rd2, off);
        rs  += __shfl_down_sync(0xffffffffu, rs,  off);
        rs2 += __shfl_down_sync(0xffffffffu, rs2, off);
    }
    __shared__ double sp[8][4];
    const int lane = threadIdx.x & 31, wid = threadIdx.x >> 5;
    if (lane == 0) { sp[wid][0] = rd; sp[wid][1] = rd2; sp[wid][2] = rs; sp[wid][3] = rs2; }
    __syncthreads();
    if (threadIdx.x == 0) {
        double a0 = 0, a1 = 0, a2 = 0, a3 = 0;
        for (int i = 0; i < 8; i++) { a0 += sp[i][0]; a1 += sp[i][1]; a2 += sp[i][2]; a3 += sp[i][3]; }
        atomicAdd(&g_acc[b][0], a0); atomicAdd(&g_acc[b][1], a1);
        atomicAdd(&g_acc[b][2], a2); atomicAdd(&g_acc[b][3], a3);
    }
}

__global__ void finalize_kernel() {
    const int b = threadIdx.x;
    if (b < BATCH) {
        const double n = (double)HXW;
        double md = g_acc[b][0] / n;
        double vd = (g_acc[b][1] - n * md * md) / (n - 1.0);
        double ms = g_acc[b][2] / n;
        double vs = (g_acc[b][3] - n * ms * ms) / (n - 1.0);
        g_norm[b] = make_float4((float)md, (float)(1.0 / (sqrt(vd) + 1e-6)),
                                (float)ms, (float)(1.0 / (sqrt(vs) + 1e-6)));
    }
}

// ---------------- stage 2 helpers ----------------
__device__ __forceinline__ void ln16(float* x, const float* g, const float* b) {
    float m = 0.f;
#pragma unroll
    for (int j = 0; j < 16; j++) m += x[j];
    m *= 0.0625f;
    float v = 0.f;
#pragma unroll
    for (int j = 0; j < 16; j++) { float d = x[j] - m; v = fmaf(d, d, v); }
    v *= 0.0625f;
    const float r = rsqrtf(v + 1e-5f);
#pragma unroll
    for (int j = 0; j < 16; j++) x[j] = (x[j] - m) * r * g[j] + b[j];
}

// gelu via HW tanh (MUFU.TANH): 0.5x(1+tanh(sqrt(2/pi)(x+0.044715x^3)))
__device__ __forceinline__ float gelu_fast(float x) {
    const float g = 0.7978845608028654f * fmaf(0.044715f * x, x * x, x);
    float th;
    asm("tanh.approx.f32 %0, %1;" : "=f"(th) : "f"(g));
    return 0.5f * x * (1.0f + th);
}

// ---------------- stage 2: per-patch transformer/MoE ----------------
__global__ void __launch_bounds__(TPB, 2)
moe_kernel(const float* __restrict__ depth, float* __restrict__ out) {
    extern __shared__ __align__(16) unsigned char dsm[];
    SW& w = *(SW*)dsm;
    float* s_k = (float*)(dsm + SK_OFF);      // [TPB][KSTR]
    float* s_v = (float*)(dsm + SV_OFF);      // [TPB][KSTR]
    float* s_x = (float*)(dsm + SX_OFF);      // overlay on s_k
    float* s_st = (float*)(dsm + SSTAT_OFF);  // [32][48] overlay on s_v
    float* s_hid = (float*)(dsm + SHID_OFF);  // [32][16]
    double* s_gate = (double*)(dsm + SGATE_OFF);

    const int tid = threadIdx.x;
    for (int i = tid; i < NWFLOATS; i += TPB) ((float*)&w)[i] = g_wblob[i];
    if (tid < 3) s_gate[tid] = 0.0;
    __syncthreads();                                         // S0

    const int pl = tid / 9;
    const int t = tid - pl * 9;
    const int P = blockIdx.x * PPB + pl;
    const int b = P / (GRID_P * GRID_P);
    const int rem = P - b * (GRID_P * GRID_P);
    const int hh = rem / GRID_P, ww = rem - hh * GRID_P;
    const int py = hh * 3 + t / 3, px = ww * 3 + (t % 3);
    const int pix = (b * HH + py) * WW2 + px;
    const int pb = tid - t;                                  // first thread of patch

    const float4 nm = g_norm[b];
    const float dn = (depth[pix] - nm.x) * nm.y;
    const float sn = (g_semprob[pix] - nm.z) * nm.w;

    // ---- collapsed embed+LN1: r = rsqrt(var+eps), var = quadratic in (dn,sn) ----
    float rr_s;
    {
        const float var = w.mst[0]*dn*dn + 2.f*w.mst[1]*dn*sn + w.mst[2]*sn*sn
                        + 2.f*w.mst[3]*dn + 2.f*w.mst[4]*sn + w.mst[5];
        rr_s = rsqrtf(var + 1e-5f);
    }
    const ull dnd = dup2(dn), snd = dup2(sn), rr = dup2(rr_s);

    // x = r*(dn*xga + sn*xgb + xgc) + n1b
    float x[16];
    {
        const ull *A = (const ull*)w.xga, *B = (const ull*)w.xgb,
                  *C = (const ull*)w.xgc, *N = (const ull*)w.n1b;
#pragma unroll
        for (int p = 0; p < 8; p++) {
            const ull v = fma2(rr, fma2(dnd, A[p], fma2(snd, B[p], C[p])), N[p]);
            upk2(v, x[2*p], x[2*p+1]);
        }
    }

    // ---- collapsed qkv (constant port): qkv = r*(dn*qa + sn*qb + qc) + qd ----
    ull aq[8];
    {
        ull* krow = (ull*)&s_k[tid * KSTR];
        ull* vrow = (ull*)&s_v[tid * KSTR];
#pragma unroll
        for (int p = 0; p < 8; p++)
            aq[p] = fma2(rr, fma2(dnd, c_w64[CB_QA + p],
                          fma2(snd, c_w64[CB_QB + p], c_w64[CB_QC + p])), c_w64[CB_QD + p]);
#pragma unroll
        for (int p = 0; p < 8; p++)
            krow[p] = fma2(rr, fma2(dnd, c_w64[CB_QA + 8 + p],
                          fma2(snd, c_w64[CB_QB + 8 + p], c_w64[CB_QC + 8 + p])), c_w64[CB_QD + 8 + p]);
#pragma unroll
        for (int p = 0; p < 8; p++)
            vrow[p] = fma2(rr, fma2(dnd, c_w64[CB_QA + 16 + p],
                          fma2(snd, c_w64[CB_QB + 16 + p], c_w64[CB_QC + 16 + p])), c_w64[CB_QD + 16 + p]);
    }
    __syncthreads();                                         // S1

    // ---- attention ----
    float ao[16];
#pragma unroll
    for (int h = 0; h < 2; h++) {
        float sc[9]; float mx = -1e30f;
#pragma unroll
        for (int tt = 0; tt < 9; tt++) {
            const ull* kr = (const ull*)&s_k[(pb + tt) * KSTR];
            ull acc = 0ull;
#pragma unroll
            for (int p = 0; p < 4; p++) acc = fma2(aq[h*4 + p], kr[h*4 + p], acc);
            float a0, a1; upk2(acc, a0, a1);
            const float s = (a0 + a1) * 0.35355339059327373f;
            sc[tt] = s; mx = fmaxf(mx, s);
        }
        float sum = 0.f;
#pragma unroll
        for (int tt = 0; tt < 9; tt++) { sc[tt] = __expf(sc[tt] - mx); sum += sc[tt]; }
        const float inv = __fdividef(1.0f, sum);
        ull vacc[4] = {0ull, 0ull, 0ull, 0ull};
#pragma unroll
        for (int tt = 0; tt < 9; tt++) {
            const ull s2 = dup2(sc[tt]);
            const ull* vr = (const ull*)&s_v[(pb + tt) * KSTR];
#pragma unroll
            for (int p = 0; p < 4; p++) vacc[p] = fma2(s2, vr[h*4 + p], vacc[p]);
        }
#pragma unroll
        for (int p = 0; p < 4; p++) {
            float a0, a1; upk2(vacc[p], a0, a1);
            ao[h*8 + 2*p] = a0 * inv; ao[h*8 + 2*p + 1] = a1 * inv;
        }
    }
    // out projection (constant port) + residual + LN (n1 reused)
    {
        ull acc[8];
        const ull* bp = (const ull*)w.out_b;
#pragma unroll
        for (int p = 0; p < 8; p++) acc[p] = bp[p];
#pragma unroll
        for (int k = 0; k < 16; k++) {
            const ull v0 = dup2(ao[k]);
#pragma unroll
            for (int p = 0; p < 8; p++) acc[p] = fma2(v0, c_w64[CB_OUTW + k*8 + p], acc[p]);
        }
#pragma unroll
        for (int p = 0; p < 8; p++) {
            float f0, f1; upk2(acc[p], f0, f1);
            x[2*p] += f0; x[2*p+1] += f1;
        }
    }
    ln16(x, w.n1g, w.n1b);

    __syncthreads();                                         // S2: attn reads done
#pragma unroll
    for (int j = 0; j < 16; j++) s_x[tid * KSTR + j] = x[j];
    __syncthreads();                                         // S3

    // ---- gate: cooperative stats (each thread 1-2 channels) ----
#pragma unroll
    for (int cc = 0; cc < 2; cc++) {
        const int j = (cc == 0) ? t : (9 + t);
        if (cc == 0 || t < 7) {
            float vals[9]; float m = 0.f, mxv = -1e30f;
#pragma unroll
            for (int tt = 0; tt < 9; tt++) {
                const float v = s_x[(pb + tt) * KSTR + j];
                vals[tt] = v; m += v; mxv = fmaxf(mxv, v);
            }
            m *= (1.0f / 9.0f);
            float var = 0.f;
#pragma unroll
            for (int tt = 0; tt < 9; tt++) { const float d = vals[tt] - m; var = fmaf(d, d, var); }
            const float sd = sqrtf(var * 0.125f);            // ddof=1
            float* st = &s_st[pl * 48];
            st[j] = m; st[16 + j] = mxv; st[32 + j] = sd;
        }
    }
    __syncthreads();                                         // S4

    // hid: thread t<8 computes outputs t and 8+t
    if (t < 8) {
        const ull* stp = (const ull*)&s_st[pl * 48];
#pragma unroll
        for (int cc = 0; cc < 2; cc++) {
            const int i = (cc == 0) ? t : (8 + t);
            const ull* wr = (const ull*)&w.gw1t[i * 48];
            ull acc = 0ull;
#pragma unroll
            for (int p = 0; p < 24; p++) acc = fma2(stp[p], wr[p], acc);
            float a0, a1; upk2(acc, a0, a1);
            s_hid[pl * 16 + i] = gelu_fast(a0 + a1 + w.gb1[i]);
        }
    }
    __syncthreads();                                         // S5

    // logits + softmax (gw2 on constant port)
    float g0, g1, g2;
    {
        const float* cw2 = (const float*)&c_w64[CB_GW2];
        float lg0 = w.gb2[0], lg1 = w.gb2[1], lg2 = w.gb2[2];
        const float* hv = &s_hid[pl * 16];
#pragma unroll
        for (int i = 0; i < 16; i++) {
            const float h = hv[i];
            lg0 = fmaf(h, cw2[i*3 + 0], lg0);
            lg1 = fmaf(h, cw2[i*3 + 1], lg1);
            lg2 = fmaf(h, cw2[i*3 + 2], lg2);
        }
        const float mxl = fmaxf(lg0, fmaxf(lg1, lg2));
        const float e0 = __expf(lg0 - mxl), e1 = __expf(lg1 - mxl), e2 = __expf(lg2 - mxl);
        const float inv = __fdividef(1.0f, e0 + e1 + e2);
        g0 = e0 * inv; g1 = e1 * inv; g2 = e2 * inv;
    }
    if (t == 0) {
        atomicAdd(&s_gate[0], (double)g0);
        atomicAdd(&s_gate[1], (double)g1);
        atomicAdd(&s_gate[2], (double)g2);
    }

    // ---- experts: all W1/W2 on the constant port; vectors on smem port ----
    ull moe[8];
    {
        const ull g0d = dup2(g0), g1d = dup2(g1), g2d = dup2(g2);
        const ull *bg = (const ull*)w.b2g, *bs = (const ull*)w.b2s, *bf = (const ull*)w.b2f;
#pragma unroll
        for (int p = 0; p < 8; p++)
            moe[p] = fma2(g0d, bg[p], fma2(g1d, bs[p], fma2(g2d, bf[p], 0ull)));
    }

#define EXPERT_C(B1, B2, AA, BB, CC, GE) {                                \
        ull h_[8];                                                        \
        {                                                                 \
            const ull *Ap = (const ull*)(AA), *Bp = (const ull*)(BB),     \
                      *Cp = (const ull*)(CC);                             \
            _Pragma("unroll") for (int p = 0; p < 8; p++)                 \
                h_[p] = fma2(dnd, Ap[p], fma2(snd, Bp[p], Cp[p]));        \
        }                                                                 \
        _Pragma("unroll") for (int k = 0; k < 16; k++) {                  \
            const ull xv = dup2(x[k]);                                    \
            _Pragma("unroll") for (int p = 0; p < 8; p++)                 \
                h_[p] = fma2(xv, c_w64[(B1) + k*8 + p], h_[p]);           \
        }                                                                 \
        float hf[16];                                                     \
        _Pragma("unroll") for (int p = 0; p < 8; p++) {                   \
            float a0, a1; upk2(h_[p], a0, a1);                            \
            hf[2*p] = gelu_fast(a0) * (GE); hf[2*p+1] = gelu_fast(a1) * (GE); \
        }                                                                 \
        _Pragma("unroll") for (int k = 0; k < 16; k++) {                  \
            const ull v0 = dup2(hf[k]);                                   \
            _Pragma("unroll") for (int p = 0; p < 8; p++)                 \
                moe[p] = fma2(v0, c_w64[(B2) + k*8 + p], moe[p]);         \
        }                                                                 \
    }

    EXPERT_C(CB_EG1, CB_EG2, w.Ag, w.Bg, w.Cg, g0)
    EXPERT_C(CB_ES1, CB_ES2, w.As, w.Bs, w.Cs, g1)
    EXPERT_C(CB_EF1, CB_EF2, w.Af, w.Bf, w.Cf, g2)
#undef EXPERT_C

    // ---- final: residual folds + LN + project + sigmoid ----
    {
        const ull two = dup2(2.0f);
        const ull gdp = dup2(g0 + g2);
        const ull gsp = dup2(g1 + g2);
        const ull *dw = (const ull*)w.dpw, *db = (const ull*)w.dpb;
        const ull *sw = (const ull*)w.spw, *sb = (const ull*)w.spb;
        float mf[16];
#pragma unroll
        for (int p = 0; p < 8; p++) {
            ull v = fma2(two, pk2(x[2*p], x[2*p+1]), moe[p]);
            const ull dpf = fma2(dnd, dw[p], db[p]);
            const ull spf = fma2(snd, sw[p], sb[p]);
            v = fma2(gdp, dpf, v);
            v = fma2(gsp, spf, v);
            upk2(v, mf[2*p], mf[2*p+1]);
        }
        ln16(mf, w.n2g, w.n2b);
        const float* cpw = (const float*)&c_w64[CB_PW];
        float z = w.pb[0];
#pragma unroll
        for (int j = 0; j < 16; j++) z = fmaf(mf[j], cpw[j], z);
        out[pix] = __fdividef(1.0f, 1.0f + __expf(-z));
    }

    __syncthreads();                                         // S6
    if (tid < 3) atomicAdd(&g_gate_acc[tid], s_gate[tid]);
}

__global__ void tail_kernel(float* __restrict__ out) {
    if (threadIdx.x < 3)
        out[NPIX + threadIdx.x] = (float)(g_gate_acc[threadIdx.x] / (double)NPATCH);
}

// ---------------- launch ----------------
extern "C" void kernel_launch(void* const* d_in, const int* in_sizes, int n_in,
                              void* d_out, int out_size) {
    Ptrs ptrs;
    for (int i = 0; i < 32; i++) ptrs.p[i] = (const float*)d_in[i];
    const float* depth = (const float*)d_in[0];
    const float* sem   = (const float*)d_in[1];
    float* out = (float*)d_out;

    cudaFuncSetAttribute(moe_kernel, cudaFuncAttributeMaxDynamicSharedMemorySize, SMEM_TOTAL);

    // populate constant weights from inputs (graph-capturable async D2D)
    void* caddr = nullptr;
    cudaGetSymbolAddress(&caddr, c_w64);
    cudaMemcpyAsync((char*)caddr + CB_EG1*8,  d_in[12], 1024, cudaMemcpyDeviceToDevice);  // eg_w1
    cudaMemcpyAsync((char*)caddr + CB_EG2*8,  d_in[14], 1024, cudaMemcpyDeviceToDevice);  // eg_w2
    cudaMemcpyAsync((char*)caddr + CB_ES1*8,  d_in[16], 1024, cudaMemcpyDeviceToDevice);  // es_w1
    cudaMemcpyAsync((char*)caddr + CB_ES2*8,  d_in[18], 1024, cudaMemcpyDeviceToDevice);  // es_w2
    cudaMemcpyAsync((char*)caddr + CB_EF1*8,  d_in[20], 1024, cudaMemcpyDeviceToDevice);  // ef_w1
    cudaMemcpyAsync((char*)caddr + CB_EF2*8,  d_in[22], 1024, cudaMemcpyDeviceToDevice);  // ef_w2
    cudaMemcpyAsync((char*)caddr + CB_OUTW*8, d_in[8],  1024, cudaMemcpyDeviceToDevice);  // out_w
    cudaMemcpyAsync((char*)caddr + CB_GW2*8,  d_in[28], 192,  cudaMemcpyDeviceToDevice);  // gw2
    cudaMemcpyAsync((char*)caddr + CB_PW*8,   d_in[30], 64,   cudaMemcpyDeviceToDevice);  // pw

    pack_kernel<<<1, 256>>>(ptrs);

    // qa..qd live at the head of g_wblob after pack_kernel; copy to constant.
    void* gaddr = nullptr;
    cudaGetSymbolAddress(&gaddr, g_wblob);
    cudaMemcpyAsync((char*)caddr + CB_QA*8, gaddr, 768, cudaMemcpyDeviceToDevice);

    semprob_kernel<<<NPIX / 4 / 256, 256>>>(sem, depth);
    finalize_kernel<<<1, 32>>>();
    moe_kernel<<<NPATCH / PPB, TPB, SMEM_TOTAL>>>(depth, out);
    tail_kernel<<<1, 32>>>(out);
}

// round 15
// speedup vs baseline: 1.0859x; 1.0309x over previous
#include <cuda_runtime.h>
#include <math.h>

// ---------------- problem constants ----------------
#define HH 480
#define WW2 480
#define HXW (HH*WW2)            // 230400
#define BATCH 8
#define NPIX (BATCH*HXW)        // 1843200
#define NCH 19
#define GRID_P 160
#define NPATCH (BATCH*GRID_P*GRID_P)   // 204800
#define PPB 32                  // patches per block (1 token per thread)
#define TPB (PPB*9)             // 288 threads
#define KSTR 18                 // smem row stride (floats)

typedef unsigned long long ull;

// ---------------- f32x2 helpers ----------------
__device__ __forceinline__ ull pk2(float a, float b) {
    ull r; asm("mov.b64 %0, {%1,%2};" : "=l"(r) : "f"(a), "f"(b)); return r;
}
__device__ __forceinline__ ull dup2(float a) {
    ull r; asm("mov.b64 %0, {%1,%1};" : "=l"(r) : "f"(a)); return r;
}
__device__ __forceinline__ void upk2(ull v, float& a, float& b) {
    asm("mov.b64 {%0,%1}, %2;" : "=f"(a), "=f"(b) : "l"(v));
}
__device__ __forceinline__ ull fma2(ull a, ull b, ull c) {
    ull d; asm("fma.rn.f32x2 %0, %1, %2, %3;" : "=l"(d) : "l"(a), "l"(b), "l"(c)); return d;
}

// ---------------- device scratch ----------------
__device__ float  g_semprob[NPIX];
__device__ double g_acc[BATCH][4];
__device__ double g_gate_acc[3];
__device__ float4 g_norm[BATCH];

// Broadcast weights on the CONSTANT port. Exactly 1024 ull = 8 KB.
__constant__ ull c_w64[1024];
#define CB_EG1 0
#define CB_EG2 128
#define CB_ES1 256
#define CB_ES2 384
#define CB_EF1 512
#define CB_EF2 640
#define CB_OUTW 768
#define CB_QA 896
#define CB_QB 920
#define CB_QC 944
#define CB_QD 968
#define CB_GW2 992
#define CB_PW 1016

// ---------------- packed weights (smem-resident part) ----------------
struct SW {
    float qa[48]; float qb[48]; float qc[48]; float qd[48];
    float out_b[16];
    float Ag[16]; float Bg[16]; float Cg[16];
    float As[16]; float Bs[16]; float Cs[16];
    float Af[16]; float Bf[16]; float Cf[16];
    float b2g[16]; float b2s[16]; float b2f[16];
    float gw1t[768]; float gb1[16]; float gb2[4];
    float pb[4];
    float dpw[16]; float dpb[16]; float spw[16]; float spb[16];
    float xga[16]; float xgb[16]; float xgc[16];
    float mst[8];
    float n1g[16]; float n1b[16]; float n2g[16]; float n2b[16];
};
#define NWFLOATS ((int)(sizeof(SW)/4))
__device__ float g_wblob[sizeof(SW)/4];

struct Ptrs { const float* p[32]; };

// dynamic smem layout
#define SW_BYTES ((int)sizeof(SW))
#define SK_OFF   SW_BYTES
#define SK_BYTES (TPB*KSTR*4)                 // 20736
#define SV_OFF   (SK_OFF + SK_BYTES)
#define SX_OFF    SK_OFF
#define SSTAT_OFF SV_OFF
#define SHID_OFF  (SSTAT_OFF + 32*48*4)
#define SGATE_OFF (SV_OFF + SK_BYTES)
#define SMEM_TOTAL (SGATE_OFF + 32)

// ---------------- pack weights + precompute folds ----------------
__global__ void pack_kernel(Ptrs in) {
    SW* w = (SW*)g_wblob;
    const int tid = threadIdx.x, nt = blockDim.x;
#define CP(dst, idx, n) for (int i = tid; i < (n); i += nt) (dst)[i] = in.p[idx][i];
    CP(w->out_b, 9, 16)
    CP(w->b2g, 15, 16)   CP(w->b2s, 19, 16)  CP(w->b2f, 23, 16)
    CP(w->gb1, 27, 16)
    CP(w->dpw, 2, 16) CP(w->dpb, 3, 16) CP(w->spw, 4, 16) CP(w->spb, 5, 16)
    CP(w->n1g, 10, 16) CP(w->n1b, 11, 16) CP(w->n2g, 24, 16) CP(w->n2b, 25, 16)
#undef CP
    for (int i = tid; i < 768; i += nt) {         // g_w1 [48,16] -> gw1t [16][48]
        int r = i / 48, s = i - r * 48;
        w->gw1t[i] = in.p[26][s * 16 + r];
    }
    double abar = 0, bbar = 0, cbar = 0;
    for (int k = 0; k < 16; k++) {
        abar += in.p[2][k]; bbar += in.p[4][k];
        cbar += (double)in.p[3][k] + in.p[5][k];
    }
    abar /= 16.0; bbar /= 16.0; cbar /= 16.0;

    if (tid < 48) {
        const int o = tid;
        double pa = 0, pb = 0, pc = 0, pd = in.p[7][o];
        for (int j = 0; j < 16; j++) {
            const double a0 = in.p[2][j] - abar;
            const double b0 = in.p[4][j] - bbar;
            const double c0 = ((double)in.p[3][j] + in.p[5][j]) - cbar;
            const double g = in.p[10][j];
            const double wv = in.p[6][j * 48 + o];
            pa += a0 * g * wv; pb += b0 * g * wv; pc += c0 * g * wv;
            pd += (double)in.p[11][j] * wv;
        }
        w->qa[o] = (float)pa; w->qb[o] = (float)pb;
        w->qc[o] = (float)pc; w->qd[o] = (float)pd;
    }
    if (tid >= 64 && tid < 80) {
        const int j = tid - 64;
        const double a0 = in.p[2][j] - abar;
        const double b0 = in.p[4][j] - bbar;
        const double c0 = ((double)in.p[3][j] + in.p[5][j]) - cbar;
        const double g = in.p[10][j];
        w->xga[j] = (float)(a0 * g); w->xgb[j] = (float)(b0 * g); w->xgc[j] = (float)(c0 * g);
    }
    if (tid == 96) {
        double maa = 0, mab = 0, mbb = 0, mac = 0, mbc = 0, mcc = 0;
        for (int j = 0; j < 16; j++) {
            const double a0 = in.p[2][j] - abar;
            const double b0 = in.p[4][j] - bbar;
            const double c0 = ((double)in.p[3][j] + in.p[5][j]) - cbar;
            maa += a0*a0; mab += a0*b0; mbb += b0*b0;
            mac += a0*c0; mbc += b0*c0; mcc += c0*c0;
        }
        w->mst[0] = (float)(maa/16.0); w->mst[1] = (float)(mab/16.0);
        w->mst[2] = (float)(mbb/16.0); w->mst[3] = (float)(mac/16.0);
        w->mst[4] = (float)(mbc/16.0); w->mst[5] = (float)(mcc/16.0);
        w->mst[6] = 0.f; w->mst[7] = 0.f;
    }
    if (tid >= 128 && tid < 144) {
        const int j = tid - 128;
        float ag = 0, cg = 0, bs = 0, cs = 0, af = 0, bf = 0, cf = 0;
        for (int k = 0; k < 16; k++) {
            const float eg = in.p[12][k*16 + j], es = in.p[16][k*16 + j], ef = in.p[20][k*16 + j];
            const float dpwk = in.p[2][k], dpbk = in.p[3][k];
            const float spwk = in.p[4][k], spbk = in.p[5][k];
            ag += dpwk * eg;  cg += dpbk * eg;
            bs += spwk * es;  cs += spbk * es;
            af += dpwk * ef;  bf += spwk * ef;
            cf += (dpbk + spbk) * ef;
        }
        w->Ag[j] = ag; w->Bg[j] = 0.f; w->Cg[j] = cg + in.p[13][j];
        w->As[j] = 0.f; w->Bs[j] = bs; w->Cs[j] = cs + in.p[17][j];
        w->Af[j] = af; w->Bf[j] = bf; w->Cf[j] = cf + in.p[21][j];
    }
    if (tid < 3) w->gb2[tid] = in.p[29][tid];
    if (tid == 3) w->gb2[3] = 0.f;
    if (tid == 0) w->pb[0] = in.p[31][0];
    if (tid < BATCH*4) ((double*)g_acc)[tid] = 0.0;
    if (tid < 3) g_gate_acc[tid] = 0.0;
}

// ---------------- stage 1 ----------------
__global__ void semprob_kernel(const float* __restrict__ sem,
                               const float* __restrict__ depth) {
    const int q = blockIdx.x * 256 + threadIdx.x;
    const int p4 = q * 4;
    const int b = p4 / HXW;
    const int ip = p4 - b * HXW;
    const float4* base = (const float4*)(sem + (long)b * NCH * HXW + ip);
    float4 v[NCH];
#pragma unroll
    for (int c = 0; c < NCH; c++) v[c] = __ldg(base + (long)c * (HXW/4));
    float4 mx = v[0];
#pragma unroll
    for (int c = 1; c < NCH; c++) {
        mx.x = fmaxf(mx.x, v[c].x); mx.y = fmaxf(mx.y, v[c].y);
        mx.z = fmaxf(mx.z, v[c].z); mx.w = fmaxf(mx.w, v[c].w);
    }
    float4 sum = make_float4(0.f, 0.f, 0.f, 0.f);
#pragma unroll
    for (int c = 0; c < NCH; c++) {
        sum.x += __expf(v[c].x - mx.x); sum.y += __expf(v[c].y - mx.y);
        sum.z += __expf(v[c].z - mx.z); sum.w += __expf(v[c].w - mx.w);
    }
    float4 prob;
    prob.x = __fdividef(1.0f, sum.x); prob.y = __fdividef(1.0f, sum.y);
    prob.z = __fdividef(1.0f, sum.z); prob.w = __fdividef(1.0f, sum.w);
    ((float4*)g_semprob)[q] = prob;
    const float4 d = __ldg((const float4*)depth + q);

    double rd  = (double)d.x + (double)d.y + (double)d.z + (double)d.w;
    double rd2 = (double)d.x*d.x + (double)d.y*d.y + (double)d.z*d.z + (double)d.w*d.w;
    double rs  = (double)prob.x + (double)prob.y + (double)prob.z + (double)prob.w;
    double rs2 = (double)prob.x*prob.x + (double)prob.y*prob.y
               + (double)prob.z*prob.z + (double)prob.w*prob.w;
#pragma unroll
    for (int off = 16; off > 0; off >>= 1) {
        rd  += __shfl_down_sync(0xffffffffu, rd,  off);
        rd2 += __shfl_down_sync(0xffffffffu, rd2, off);
        rs  += __shfl_down_sync(0xffffffffu, rs,  off);
        rs2 += __shfl_down_sync(0xffffffffu, rs2, off);
    }
    __shared__ double sp[8][4];
    const int lane = threadIdx.x & 31, wid = threadIdx.x >> 5;
    if (lane == 0) { sp[wid][0] = rd; sp[wid][1] = rd2; sp[wid][2] = rs; sp[wid][3] = rs2; }
    __syncthreads();
    if (threadIdx.x == 0) {
        double a0 = 0, a1 = 0, a2 = 0, a3 = 0;
        for (int i = 0; i < 8; i++) { a0 += sp[i][0]; a1 += sp[i][1]; a2 += sp[i][2]; a3 += sp[i][3]; }
        atomicAdd(&g_acc[b][0], a0); atomicAdd(&g_acc[b][1], a1);
        atomicAdd(&g_acc[b][2], a2); atomicAdd(&g_acc[b][3], a3);
    }
}

__global__ void finalize_kernel() {
    const int b = threadIdx.x;
    if (b < BATCH) {
        const double n = (double)HXW;
        double md = g_acc[b][0] / n;
        double vd = (g_acc[b][1] - n * md * md) / (n - 1.0);
        double ms = g_acc[b][2] / n;
        double vs = (g_acc[b][3] - n * ms * ms) / (n - 1.0);
        g_norm[b] = make_float4((float)md, (float)(1.0 / (sqrt(vd) + 1e-6)),
                                (float)ms, (float)(1.0 / (sqrt(vs) + 1e-6)));
    }
}

// ---------------- stage 2 helpers ----------------
__device__ __forceinline__ void ln16(float* x, const float* g, const float* b) {
    float m = 0.f;
#pragma unroll
    for (int j = 0; j < 16; j++) m += x[j];
    m *= 0.0625f;
    float v = 0.f;
#pragma unroll
    for (int j = 0; j < 16; j++) { float d = x[j] - m; v = fmaf(d, d, v); }
    v *= 0.0625f;
    const float r = rsqrtf(v + 1e-5f);
#pragma unroll
    for (int j = 0; j < 16; j++) x[j] = (x[j] - m) * r * g[j] + b[j];
}

// gelu via HW tanh (MUFU.TANH)
__device__ __forceinline__ float gelu_fast(float x) {
    const float g = 0.7978845608028654f * fmaf(0.044715f * x, x * x, x);
    float th;
    asm("tanh.approx.f32 %0, %1;" : "=f"(th) : "f"(g));
    return 0.5f * x * (1.0f + th);
}

// ---------------- stage 2: per-patch transformer/MoE ----------------
__global__ void __launch_bounds__(TPB, 3)
moe_kernel(const float* __restrict__ depth, float* __restrict__ out) {
    extern __shared__ __align__(16) unsigned char dsm[];
    SW& w = *(SW*)dsm;
    float* s_k = (float*)(dsm + SK_OFF);
    float* s_v = (float*)(dsm + SV_OFF);
    float* s_x = (float*)(dsm + SX_OFF);
    float* s_st = (float*)(dsm + SSTAT_OFF);
    float* s_hid = (float*)(dsm + SHID_OFF);
    double* s_gate = (double*)(dsm + SGATE_OFF);

    const int tid = threadIdx.x;
    for (int i = tid; i < NWFLOATS; i += TPB) ((float*)&w)[i] = g_wblob[i];
    if (tid < 3) s_gate[tid] = 0.0;
    __syncthreads();                                         // S0

    const int pl = tid / 9;
    const int t = tid - pl * 9;
    const int P = blockIdx.x * PPB + pl;
    const int b = P / (GRID_P * GRID_P);
    const int rem = P - b * (GRID_P * GRID_P);
    const int hh = rem / GRID_P, ww = rem - hh * GRID_P;
    const int py = hh * 3 + t / 3, px = ww * 3 + (t % 3);
    const int pix = (b * HH + py) * WW2 + px;
    const int pb = tid - t;

    const float4 nm = g_norm[b];
    const float dn = (depth[pix] - nm.x) * nm.y;
    const float sn = (g_semprob[pix] - nm.z) * nm.w;

    // ---- collapsed embed+LN1 variance ----
    float rr_s;
    {
        const float var = w.mst[0]*dn*dn + 2.f*w.mst[1]*dn*sn + w.mst[2]*sn*sn
                        + 2.f*w.mst[3]*dn + 2.f*w.mst[4]*sn + w.mst[5];
        rr_s = rsqrtf(var + 1e-5f);
    }
    const ull dnd = dup2(dn), snd = dup2(sn), rr = dup2(rr_s);

    // x = r*(dn*xga + sn*xgb + xgc) + n1b
    float x[16];
    {
        const ull *A = (const ull*)w.xga, *B = (const ull*)w.xgb,
                  *C = (const ull*)w.xgc, *N = (const ull*)w.n1b;
#pragma unroll
        for (int p = 0; p < 8; p++) {
            const ull v = fma2(rr, fma2(dnd, A[p], fma2(snd, B[p], C[p])), N[p]);
            upk2(v, x[2*p], x[2*p+1]);
        }
    }

    // ---- collapsed qkv (constant port) ----
    ull aq[8];
    {
        ull* krow = (ull*)&s_k[tid * KSTR];
        ull* vrow = (ull*)&s_v[tid * KSTR];
#pragma unroll
        for (int p = 0; p < 8; p++)
            aq[p] = fma2(rr, fma2(dnd, c_w64[CB_QA + p],
                          fma2(snd, c_w64[CB_QB + p], c_w64[CB_QC + p])), c_w64[CB_QD + p]);
#pragma unroll
        for (int p = 0; p < 8; p++)
            krow[p] = fma2(rr, fma2(dnd, c_w64[CB_QA + 8 + p],
                          fma2(snd, c_w64[CB_QB + 8 + p], c_w64[CB_QC + 8 + p])), c_w64[CB_QD + 8 + p]);
#pragma unroll
        for (int p = 0; p < 8; p++)
            vrow[p] = fma2(rr, fma2(dnd, c_w64[CB_QA + 16 + p],
                          fma2(snd, c_w64[CB_QB + 16 + p], c_w64[CB_QC + 16 + p])), c_w64[CB_QD + 16 + p]);
    }
    __syncthreads();                                         // S1

    // ---- attention ----
    float ao[16];
#pragma unroll
    for (int h = 0; h < 2; h++) {
        float sc[9]; float mx = -1e30f;
#pragma unroll
        for (int tt = 0; tt < 9; tt++) {
            const ull* kr = (const ull*)&s_k[(pb + tt) * KSTR];
            ull acc = 0ull;
#pragma unroll
            for (int p = 0; p < 4; p++) acc = fma2(aq[h*4 + p], kr[h*4 + p], acc);
            float a0, a1; upk2(acc, a0, a1);
            const float s = (a0 + a1) * 0.35355339059327373f;
            sc[tt] = s; mx = fmaxf(mx, s);
        }
        float sum = 0.f;
#pragma unroll
        for (int tt = 0; tt < 9; tt++) { sc[tt] = __expf(sc[tt] - mx); sum += sc[tt]; }
        const float inv = __fdividef(1.0f, sum);
        ull vacc[4] = {0ull, 0ull, 0ull, 0ull};
#pragma unroll
        for (int tt = 0; tt < 9; tt++) {
            const ull s2 = dup2(sc[tt]);
            const ull* vr = (const ull*)&s_v[(pb + tt) * KSTR];
#pragma unroll
            for (int p = 0; p < 4; p++) vacc[p] = fma2(s2, vr[h*4 + p], vacc[p]);
        }
#pragma unroll
        for (int p = 0; p < 4; p++) {
            float a0, a1; upk2(vacc[p], a0, a1);
            ao[h*8 + 2*p] = a0 * inv; ao[h*8 + 2*p + 1] = a1 * inv;
        }
    }
    // out projection (constant port) + residual + LN
    {
        ull acc[8];
        const ull* bp = (const ull*)w.out_b;
#pragma unroll
        for (int p = 0; p < 8; p++) acc[p] = bp[p];
#pragma unroll
        for (int k = 0; k < 16; k++) {
            const ull v0 = dup2(ao[k]);
#pragma unroll
            for (int p = 0; p < 8; p++) acc[p] = fma2(v0, c_w64[CB_OUTW + k*8 + p], acc[p]);
        }
#pragma unroll
        for (int p = 0; p < 8; p++) {
            float f0, f1; upk2(acc[p], f0, f1);
            x[2*p] += f0; x[2*p+1] += f1;
        }
    }
    ln16(x, w.n1g, w.n1b);

    __syncthreads();                                         // S2
#pragma unroll
    for (int j = 0; j < 16; j++) s_x[tid * KSTR + j] = x[j];
    __syncthreads();                                         // S3
    // x registers are DEAD from here: experts and final read from s_x.

    // ---- gate: cooperative stats ----
#pragma unroll
    for (int cc = 0; cc < 2; cc++) {
        const int j = (cc == 0) ? t : (9 + t);
        if (cc == 0 || t < 7) {
            float vals[9]; float m = 0.f, mxv = -1e30f;
#pragma unroll
            for (int tt = 0; tt < 9; tt++) {
                const float v = s_x[(pb + tt) * KSTR + j];
                vals[tt] = v; m += v; mxv = fmaxf(mxv, v);
            }
            m *= (1.0f / 9.0f);
            float var = 0.f;
#pragma unroll
            for (int tt = 0; tt < 9; tt++) { const float d = vals[tt] - m; var = fmaf(d, d, var); }
            const float sd = sqrtf(var * 0.125f);
            float* st = &s_st[pl * 48];
            st[j] = m; st[16 + j] = mxv; st[32 + j] = sd;
        }
    }
    __syncthreads();                                         // S4

    if (t < 8) {
        const ull* stp = (const ull*)&s_st[pl * 48];
#pragma unroll
        for (int cc = 0; cc < 2; cc++) {
            const int i = (cc == 0) ? t : (8 + t);
            const ull* wr = (const ull*)&w.gw1t[i * 48];
            ull acc = 0ull;
#pragma unroll
            for (int p = 0; p < 24; p++) acc = fma2(stp[p], wr[p], acc);
            float a0, a1; upk2(acc, a0, a1);
            s_hid[pl * 16 + i] = gelu_fast(a0 + a1 + w.gb1[i]);
        }
    }
    __syncthreads();                                         // S5

    // logits + softmax (gw2 on constant port)
    float g0, g1, g2;
    {
        const float* cw2 = (const float*)&c_w64[CB_GW2];
        float lg0 = w.gb2[0], lg1 = w.gb2[1], lg2 = w.gb2[2];
        const float* hv = &s_hid[pl * 16];
#pragma unroll
        for (int i = 0; i < 16; i++) {
            const float h = hv[i];
            lg0 = fmaf(h, cw2[i*3 + 0], lg0);
            lg1 = fmaf(h, cw2[i*3 + 1], lg1);
            lg2 = fmaf(h, cw2[i*3 + 2], lg2);
        }
        const float mxl = fmaxf(lg0, fmaxf(lg1, lg2));
        const float e0 = __expf(lg0 - mxl), e1 = __expf(lg1 - mxl), e2 = __expf(lg2 - mxl);
        const float inv = __fdividef(1.0f, e0 + e1 + e2);
        g0 = e0 * inv; g1 = e1 * inv; g2 = e2 * inv;
    }
    if (t == 0) {
        atomicAdd(&s_gate[0], (double)g0);
        atomicAdd(&s_gate[1], (double)g1);
        atomicAdd(&s_gate[2], (double)g2);
    }

    // ---- experts: W1/W2 on constant port; x read back from s_x ----
    const int rx = tid * KSTR;
    ull moe[8];
    {
        const ull g0d = dup2(g0), g1d = dup2(g1), g2d = dup2(g2);
        const ull *bg = (const ull*)w.b2g, *bs = (const ull*)w.b2s, *bf = (const ull*)w.b2f;
#pragma unroll
        for (int p = 0; p < 8; p++)
            moe[p] = fma2(g0d, bg[p], fma2(g1d, bs[p], fma2(g2d, bf[p], 0ull)));
    }

#define EXPERT_C(B1, B2, AA, BB, CC, GE) {                                \
        ull h_[8];                                                        \
        {                                                                 \
            const ull *Ap = (const ull*)(AA), *Bp = (const ull*)(BB),     \
                      *Cp = (const ull*)(CC);                             \
            _Pragma("unroll") for (int p = 0; p < 8; p++)                 \
                h_[p] = fma2(dnd, Ap[p], fma2(snd, Bp[p], Cp[p]));        \
        }                                                                 \
        _Pragma("unroll") for (int k = 0; k < 16; k++) {                  \
            const ull xv = dup2(s_x[rx + k]);                             \
            _Pragma("unroll") for (int p = 0; p < 8; p++)                 \
                h_[p] = fma2(xv, c_w64[(B1) + k*8 + p], h_[p]);           \
        }                                                                 \
        float hf[16];                                                     \
        _Pragma("unroll") for (int p = 0; p < 8; p++) {                   \
            float a0, a1; upk2(h_[p], a0, a1);                            \
            hf[2*p] = gelu_fast(a0) * (GE); hf[2*p+1] = gelu_fast(a1) * (GE); \
        }                                                                 \
        _Pragma("unroll") for (int k = 0; k < 16; k++) {                  \
            const ull v0 = dup2(hf[k]);                                   \
            _Pragma("unroll") for (int p = 0; p < 8; p++)                 \
                moe[p] = fma2(v0, c_w64[(B2) + k*8 + p], moe[p]);         \
        }                                                                 \
    }

    EXPERT_C(CB_EG1, CB_EG2, w.Ag, w.Bg, w.Cg, g0)
    EXPERT_C(CB_ES1, CB_ES2, w.As, w.Bs, w.Cs, g1)
    EXPERT_C(CB_EF1, CB_EF2, w.Af, w.Bf, w.Cf, g2)
#undef EXPERT_C

    // ---- final: residual folds + LN + project + sigmoid (x from s_x) ----
    {
        const ull* xr = (const ull*)&s_x[rx];
        const ull two = dup2(2.0f);
        const ull gdp = dup2(g0 + g2);
        const ull gsp = dup2(g1 + g2);
        const ull *dw = (const ull*)w.dpw, *db = (const ull*)w.dpb;
        const ull *sw = (const ull*)w.spw, *sb = (const ull*)w.spb;
        float mf[16];
#pragma unroll
        for (int p = 0; p < 8; p++) {
            ull v = fma2(two, xr[p], moe[p]);
            const ull dpf = fma2(dnd, dw[p], db[p]);
            const ull spf = fma2(snd, sw[p], sb[p]);
            v = fma2(gdp, dpf, v);
            v = fma2(gsp, spf, v);
            upk2(v, mf[2*p], mf[2*p+1]);
        }
        ln16(mf, w.n2g, w.n2b);
        const float* cpw = (const float*)&c_w64[CB_PW];
        float z = w.pb[0];
#pragma unroll
        for (int j = 0; j < 16; j++) z = fmaf(mf[j], cpw[j], z);
        out[pix] = __fdividef(1.0f, 1.0f + __expf(-z));
    }

    __syncthreads();                                         // S6
    if (tid < 3) atomicAdd(&g_gate_acc[tid], s_gate[tid]);
}

__global__ void tail_kernel(float* __restrict__ out) {
    if (threadIdx.x < 3)
        out[NPIX + threadIdx.x] = (float)(g_gate_acc[threadIdx.x] / (double)NPATCH);
}

// ---------------- launch ----------------
extern "C" void kernel_launch(void* const* d_in, const int* in_sizes, int n_in,
                              void* d_out, int out_size) {
    Ptrs ptrs;
    for (int i = 0; i < 32; i++) ptrs.p[i] = (const float*)d_in[i];
    const float* depth = (const float*)d_in[0];
    const float* sem   = (const float*)d_in[1];
    float* out = (float*)d_out;

    cudaFuncSetAttribute(moe_kernel, cudaFuncAttributeMaxDynamicSharedMemorySize, SMEM_TOTAL);

    // populate constant weights from inputs (graph-capturable async D2D)
    void* caddr = nullptr;
    cudaGetSymbolAddress(&caddr, c_w64);
    cudaMemcpyAsync((char*)caddr + CB_EG1*8,  d_in[12], 1024, cudaMemcpyDeviceToDevice);
    cudaMemcpyAsync((char*)caddr + CB_EG2*8,  d_in[14], 1024, cudaMemcpyDeviceToDevice);
    cudaMemcpyAsync((char*)caddr + CB_ES1*8,  d_in[16], 1024, cudaMemcpyDeviceToDevice);
    cudaMemcpyAsync((char*)caddr + CB_ES2*8,  d_in[18], 1024, cudaMemcpyDeviceToDevice);
    cudaMemcpyAsync((char*)caddr + CB_EF1*8,  d_in[20], 1024, cudaMemcpyDeviceToDevice);
    cudaMemcpyAsync((char*)caddr + CB_EF2*8,  d_in[22], 1024, cudaMemcpyDeviceToDevice);
    cudaMemcpyAsync((char*)caddr + CB_OUTW*8, d_in[8],  1024, cudaMemcpyDeviceToDevice);
    cudaMemcpyAsync((char*)caddr + CB_GW2*8,  d_in[28], 192,  cudaMemcpyDeviceToDevice);
    cudaMemcpyAsync((char*)caddr + CB_PW*8,   d_in[30], 64,   cudaMemcpyDeviceToDevice);

    pack_kernel<<<1, 256>>>(ptrs);

    void* gaddr = nullptr;
    cudaGetSymbolAddress(&gaddr, g_wblob);
    cudaMemcpyAsync((char*)caddr + CB_QA*8, gaddr, 768, cudaMemcpyDeviceToDevice);

    semprob_kernel<<<NPIX / 4 / 256, 256>>>(sem, depth);
    finalize_kernel<<<1, 32>>>();
    moe_kernel<<<NPATCH / PPB, TPB, SMEM_TOTAL>>>(depth, out);
    tail_kernel<<<1, 32>>>(out);
}

// round 16
// speedup vs baseline: 1.1180x; 1.0295x over previous
#include <cuda_runtime.h>
#include <math.h>

// ---------------- problem constants ----------------
#define HH 480
#define WW2 480
#define HXW (HH*WW2)            // 230400
#define BATCH 8
#define NPIX (BATCH*HXW)        // 1843200
#define NCH 19
#define GRID_P 160
#define NPATCH (BATCH*GRID_P*GRID_P)   // 204800
#define PPB 64                  // patches per block (2 tokens per thread)
#define TPB 288                 // threads
#define NROWS (PPB*9)           // 576 rows
#define KSTR 18                 // smem row stride (floats)

typedef unsigned long long ull;

// ---------------- f32x2 helpers ----------------
__device__ __forceinline__ ull pk2(float a, float b) {
    ull r; asm("mov.b64 %0, {%1,%2};" : "=l"(r) : "f"(a), "f"(b)); return r;
}
__device__ __forceinline__ ull dup2(float a) {
    ull r; asm("mov.b64 %0, {%1,%1};" : "=l"(r) : "f"(a)); return r;
}
__device__ __forceinline__ void upk2(ull v, float& a, float& b) {
    asm("mov.b64 {%0,%1}, %2;" : "=f"(a), "=f"(b) : "l"(v));
}
__device__ __forceinline__ ull fma2(ull a, ull b, ull c) {
    ull d; asm("fma.rn.f32x2 %0, %1, %2, %3;" : "=l"(d) : "l"(a), "l"(b), "l"(c)); return d;
}

// ---------------- device scratch ----------------
__device__ float  g_semprob[NPIX];
__device__ double g_acc[BATCH][4];
__device__ double g_gate_acc[3];
__device__ float4 g_norm[BATCH];

// Broadcast weights on the CONSTANT port. Exactly 1024 ull = 8 KB.
__constant__ ull c_w64[1024];
#define CB_EG1 0
#define CB_EG2 128
#define CB_ES1 256
#define CB_ES2 384
#define CB_EF1 512
#define CB_EF2 640
#define CB_OUTW 768
#define CB_QA 896
#define CB_QB 920
#define CB_QC 944
#define CB_QD 968
#define CB_GW2 992
#define CB_PW 1016

// ---------------- packed weights (smem-resident part) ----------------
struct SW {
    float qa[48]; float qb[48]; float qc[48]; float qd[48];
    float out_b[16];
    float Ag[16]; float Bg[16]; float Cg[16];
    float As[16]; float Bs[16]; float Cs[16];
    float Af[16]; float Bf[16]; float Cf[16];
    float b2g[16]; float b2s[16]; float b2f[16];
    float gw1t[768]; float gb1[16]; float gb2[4];
    float pb[4];
    float dpw[16]; float dpb[16]; float spw[16]; float spb[16];
    float xga[16]; float xgb[16]; float xgc[16];
    float mst[8];
    float n1g[16]; float n1b[16]; float n2g[16]; float n2b[16];
};
#define NWFLOATS ((int)(sizeof(SW)/4))
__device__ float g_wblob[sizeof(SW)/4];

struct Ptrs { const float* p[32]; };

// dynamic smem layout
#define SW_BYTES ((int)sizeof(SW))
#define SK_OFF   SW_BYTES
#define SK_BYTES (NROWS*KSTR*4)               // 41472
#define SV_OFF   (SK_OFF + SK_BYTES)
#define SX_OFF    SK_OFF                      // x rows overlay on s_k
#define SSTAT_OFF SV_OFF                      // [64][48] overlay on s_v
#define SHID_OFF  (SSTAT_OFF + 64*48*4)       // [64][16]
#define SGATE_OFF (SV_OFF + SK_BYTES)
#define SMEM_TOTAL (SGATE_OFF + 32)

// ---------------- pack weights + precompute folds ----------------
__global__ void pack_kernel(Ptrs in) {
    SW* w = (SW*)g_wblob;
    const int tid = threadIdx.x, nt = blockDim.x;
#define CP(dst, idx, n) for (int i = tid; i < (n); i += nt) (dst)[i] = in.p[idx][i];
    CP(w->out_b, 9, 16)
    CP(w->b2g, 15, 16)   CP(w->b2s, 19, 16)  CP(w->b2f, 23, 16)
    CP(w->gb1, 27, 16)
    CP(w->dpw, 2, 16) CP(w->dpb, 3, 16) CP(w->spw, 4, 16) CP(w->spb, 5, 16)
    CP(w->n1g, 10, 16) CP(w->n1b, 11, 16) CP(w->n2g, 24, 16) CP(w->n2b, 25, 16)
#undef CP
    for (int i = tid; i < 768; i += nt) {         // g_w1 [48,16] -> gw1t [16][48]
        int r = i / 48, s = i - r * 48;
        w->gw1t[i] = in.p[26][s * 16 + r];
    }
    double abar = 0, bbar = 0, cbar = 0;
    for (int k = 0; k < 16; k++) {
        abar += in.p[2][k]; bbar += in.p[4][k];
        cbar += (double)in.p[3][k] + in.p[5][k];
    }
    abar /= 16.0; bbar /= 16.0; cbar /= 16.0;

    if (tid < 48) {
        const int o = tid;
        double pa = 0, pb = 0, pc = 0, pd = in.p[7][o];
        for (int j = 0; j < 16; j++) {
            const double a0 = in.p[2][j] - abar;
            const double b0 = in.p[4][j] - bbar;
            const double c0 = ((double)in.p[3][j] + in.p[5][j]) - cbar;
            const double g = in.p[10][j];
            const double wv = in.p[6][j * 48 + o];
            pa += a0 * g * wv; pb += b0 * g * wv; pc += c0 * g * wv;
            pd += (double)in.p[11][j] * wv;
        }
        w->qa[o] = (float)pa; w->qb[o] = (float)pb;
        w->qc[o] = (float)pc; w->qd[o] = (float)pd;
    }
    if (tid >= 64 && tid < 80) {
        const int j = tid - 64;
        const double a0 = in.p[2][j] - abar;
        const double b0 = in.p[4][j] - bbar;
        const double c0 = ((double)in.p[3][j] + in.p[5][j]) - cbar;
        const double g = in.p[10][j];
        w->xga[j] = (float)(a0 * g); w->xgb[j] = (float)(b0 * g); w->xgc[j] = (float)(c0 * g);
    }
    if (tid == 96) {
        double maa = 0, mab = 0, mbb = 0, mac = 0, mbc = 0, mcc = 0;
        for (int j = 0; j < 16; j++) {
            const double a0 = in.p[2][j] - abar;
            const double b0 = in.p[4][j] - bbar;
            const double c0 = ((double)in.p[3][j] + in.p[5][j]) - cbar;
            maa += a0*a0; mab += a0*b0; mbb += b0*b0;
            mac += a0*c0; mbc += b0*c0; mcc += c0*c0;
        }
        w->mst[0] = (float)(maa/16.0); w->mst[1] = (float)(mab/16.0);
        w->mst[2] = (float)(mbb/16.0); w->mst[3] = (float)(mac/16.0);
        w->mst[4] = (float)(mbc/16.0); w->mst[5] = (float)(mcc/16.0);
        w->mst[6] = 0.f; w->mst[7] = 0.f;
    }
    if (tid >= 128 && tid < 144) {
        const int j = tid - 128;
        float ag = 0, cg = 0, bs = 0, cs = 0, af = 0, bf = 0, cf = 0;
        for (int k = 0; k < 16; k++) {
            const float eg = in.p[12][k*16 + j], es = in.p[16][k*16 + j], ef = in.p[20][k*16 + j];
            const float dpwk = in.p[2][k], dpbk = in.p[3][k];
            const float spwk = in.p[4][k], spbk = in.p[5][k];
            ag += dpwk * eg;  cg += dpbk * eg;
            bs += spwk * es;  cs += spbk * es;
            af += dpwk * ef;  bf += spwk * ef;
            cf += (dpbk + spbk) * ef;
        }
        w->Ag[j] = ag; w->Bg[j] = 0.f; w->Cg[j] = cg + in.p[13][j];
        w->As[j] = 0.f; w->Bs[j] = bs; w->Cs[j] = cs + in.p[17][j];
        w->Af[j] = af; w->Bf[j] = bf; w->Cf[j] = cf + in.p[21][j];
    }
    if (tid < 3) w->gb2[tid] = in.p[29][tid];
    if (tid == 3) w->gb2[3] = 0.f;
    if (tid == 0) w->pb[0] = in.p[31][0];
    if (tid < BATCH*4) ((double*)g_acc)[tid] = 0.0;
    if (tid < 3) g_gate_acc[tid] = 0.0;
}

// ---------------- stage 1 ----------------
__global__ void semprob_kernel(const float* __restrict__ sem,
                               const float* __restrict__ depth) {
    const int q = blockIdx.x * 256 + threadIdx.x;
    const int p4 = q * 4;
    const int b = p4 / HXW;
    const int ip = p4 - b * HXW;
    const float4* base = (const float4*)(sem + (long)b * NCH * HXW + ip);
    float4 v[NCH];
#pragma unroll
    for (int c = 0; c < NCH; c++) v[c] = __ldg(base + (long)c * (HXW/4));
    float4 mx = v[0];
#pragma unroll
    for (int c = 1; c < NCH; c++) {
        mx.x = fmaxf(mx.x, v[c].x); mx.y = fmaxf(mx.y, v[c].y);
        mx.z = fmaxf(mx.z, v[c].z); mx.w = fmaxf(mx.w, v[c].w);
    }
    float4 sum = make_float4(0.f, 0.f, 0.f, 0.f);
#pragma unroll
    for (int c = 0; c < NCH; c++) {
        sum.x += __expf(v[c].x - mx.x); sum.y += __expf(v[c].y - mx.y);
        sum.z += __expf(v[c].z - mx.z); sum.w += __expf(v[c].w - mx.w);
    }
    float4 prob;
    prob.x = __fdividef(1.0f, sum.x); prob.y = __fdividef(1.0f, sum.y);
    prob.z = __fdividef(1.0f, sum.z); prob.w = __fdividef(1.0f, sum.w);
    ((float4*)g_semprob)[q] = prob;
    const float4 d = __ldg((const float4*)depth + q);

    double rd  = (double)d.x + (double)d.y + (double)d.z + (double)d.w;
    double rd2 = (double)d.x*d.x + (double)d.y*d.y + (double)d.z*d.z + (double)d.w*d.w;
    double rs  = (double)prob.x + (double)prob.y + (double)prob.z + (double)prob.w;
    double rs2 = (double)prob.x*prob.x + (double)prob.y*prob.y
               + (double)prob.z*prob.z + (double)prob.w*prob.w;
#pragma unroll
    for (int off = 16; off > 0; off >>= 1) {
        rd  += __shfl_down_sync(0xffffffffu, rd,  off);
        rd2 += __shfl_down_sync(0xffffffffu, rd2, off);
        rs  += __shfl_down_sync(0xffffffffu, rs,  off);
        rs2 += __shfl_down_sync(0xffffffffu, rs2, off);
    }
    __shared__ double sp[8][4];
    const int lane = threadIdx.x & 31, wid = threadIdx.x >> 5;
    if (lane == 0) { sp[wid][0] = rd; sp[wid][1] = rd2; sp[wid][2] = rs; sp[wid][3] = rs2; }
    __syncthreads();
    if (threadIdx.x == 0) {
        double a0 = 0, a1 = 0, a2 = 0, a3 = 0;
        for (int i = 0; i < 8; i++) { a0 += sp[i][0]; a1 += sp[i][1]; a2 += sp[i][2]; a3 += sp[i][3]; }
        atomicAdd(&g_acc[b][0], a0); atomicAdd(&g_acc[b][1], a1);
        atomicAdd(&g_acc[b][2], a2); atomicAdd(&g_acc[b][3], a3);
    }
}

__global__ void finalize_kernel() {
    const int b = threadIdx.x;
    if (b < BATCH) {
        const double n = (double)HXW;
        double md = g_acc[b][0] / n;
        double vd = (g_acc[b][1] - n * md * md) / (n - 1.0);
        double ms = g_acc[b][2] / n;
        double vs = (g_acc[b][3] - n * ms * ms) / (n - 1.0);
        g_norm[b] = make_float4((float)md, (float)(1.0 / (sqrt(vd) + 1e-6)),
                                (float)ms, (float)(1.0 / (sqrt(vs) + 1e-6)));
    }
}

// ---------------- stage 2 helpers ----------------
__device__ __forceinline__ void ln16(float* x, const float* g, const float* b) {
    float m = 0.f;
#pragma unroll
    for (int j = 0; j < 16; j++) m += x[j];
    m *= 0.0625f;
    float v = 0.f;
#pragma unroll
    for (int j = 0; j < 16; j++) { float d = x[j] - m; v = fmaf(d, d, v); }
    v *= 0.0625f;
    const float r = rsqrtf(v + 1e-5f);
#pragma unroll
    for (int j = 0; j < 16; j++) x[j] = (x[j] - m) * r * g[j] + b[j];
}

// gelu via HW tanh (MUFU.TANH)
__device__ __forceinline__ float gelu_fast(float x) {
    const float g = 0.7978845608028654f * fmaf(0.044715f * x, x * x, x);
    float th;
    asm("tanh.approx.f32 %0, %1;" : "=f"(th) : "f"(g));
    return 0.5f * x * (1.0f + th);
}

// ---------------- stage 2: per-patch transformer/MoE (2 tokens/thread) ----------------
__global__ void __launch_bounds__(TPB, 2)
moe_kernel(const float* __restrict__ depth, float* __restrict__ out) {
    extern __shared__ __align__(16) unsigned char dsm[];
    SW& w = *(SW*)dsm;
    float* s_k = (float*)(dsm + SK_OFF);      // [576][KSTR]
    float* s_v = (float*)(dsm + SV_OFF);      // [576][KSTR]
    float* s_x = (float*)(dsm + SX_OFF);      // overlay on s_k after attention
    float* s_st = (float*)(dsm + SSTAT_OFF);  // [64][48]
    float* s_hid = (float*)(dsm + SHID_OFF);  // [64][16]
    double* s_gate = (double*)(dsm + SGATE_OFF);

    const int tid = threadIdx.x;
    for (int i = tid; i < NWFLOATS; i += TPB) ((float*)&w)[i] = g_wblob[i];
    if (tid < 3) s_gate[tid] = 0.0;
    __syncthreads();                                         // S0

    const int pl = tid / 9;
    const int t = tid - pl * 9;
    const int pbrow = tid - t;                 // = pl*9
    const int rowA = tid, rowB = tid + 288;

    float dn_[2], sn_[2], rr_[2];
    int pix_[2];
#pragma unroll
    for (int tok = 0; tok < 2; tok++) {
        const int P = blockIdx.x * PPB + pl + tok * 32;
        const int b = P / (GRID_P * GRID_P);
        const int rem = P - b * (GRID_P * GRID_P);
        const int hh = rem / GRID_P, ww = rem - hh * GRID_P;
        const int py = hh * 3 + t / 3, px = ww * 3 + (t % 3);
        const int pix = (b * HH + py) * WW2 + px;
        pix_[tok] = pix;
        const float4 nm = g_norm[b];
        const float dn = (depth[pix] - nm.x) * nm.y;
        const float sn = (g_semprob[pix] - nm.z) * nm.w;
        dn_[tok] = dn; sn_[tok] = sn;
        const float var = w.mst[0]*dn*dn + 2.f*w.mst[1]*dn*sn + w.mst[2]*sn*sn
                        + 2.f*w.mst[3]*dn + 2.f*w.mst[4]*sn + w.mst[5];
        rr_[tok] = rsqrtf(var + 1e-5f);
    }

    // ---- collapsed qkv for BOTH tokens (constant weights loaded once) ----
    ull aq[2][8];
    {
        const ull d0 = dup2(dn_[0]), s0 = dup2(sn_[0]), r0 = dup2(rr_[0]);
        const ull d1 = dup2(dn_[1]), s1 = dup2(sn_[1]), r1 = dup2(rr_[1]);
        ull* kA = (ull*)&s_k[rowA * KSTR]; ull* kB = (ull*)&s_k[rowB * KSTR];
        ull* vA = (ull*)&s_v[rowA * KSTR]; ull* vB = (ull*)&s_v[rowB * KSTR];
#pragma unroll
        for (int p = 0; p < 8; p++) {
            const ull A = c_w64[CB_QA + p], B = c_w64[CB_QB + p],
                      C = c_w64[CB_QC + p], D = c_w64[CB_QD + p];
            aq[0][p] = fma2(r0, fma2(d0, A, fma2(s0, B, C)), D);
            aq[1][p] = fma2(r1, fma2(d1, A, fma2(s1, B, C)), D);
        }
#pragma unroll
        for (int p = 0; p < 8; p++) {
            const ull A = c_w64[CB_QA + 8 + p], B = c_w64[CB_QB + 8 + p],
                      C = c_w64[CB_QC + 8 + p], D = c_w64[CB_QD + 8 + p];
            kA[p] = fma2(r0, fma2(d0, A, fma2(s0, B, C)), D);
            kB[p] = fma2(r1, fma2(d1, A, fma2(s1, B, C)), D);
        }
#pragma unroll
        for (int p = 0; p < 8; p++) {
            const ull A = c_w64[CB_QA + 16 + p], B = c_w64[CB_QB + 16 + p],
                      C = c_w64[CB_QC + 16 + p], D = c_w64[CB_QD + 16 + p];
            vA[p] = fma2(r0, fma2(d0, A, fma2(s0, B, C)), D);
            vB[p] = fma2(r1, fma2(d1, A, fma2(s1, B, C)), D);
        }
    }
    __syncthreads();                                         // S1

    // ---- attention (sequential per token; x NOT live here) ----
    float ao[2][16];
#pragma unroll
    for (int tok = 0; tok < 2; tok++) {
        const int rb = pbrow + tok * 288;
#pragma unroll
        for (int h = 0; h < 2; h++) {
            float sc[9]; float mx = -1e30f;
#pragma unroll
            for (int tt = 0; tt < 9; tt++) {
                const ull* kr = (const ull*)&s_k[(rb + tt) * KSTR];
                ull acc = 0ull;
#pragma unroll
                for (int p = 0; p < 4; p++) acc = fma2(aq[tok][h*4 + p], kr[h*4 + p], acc);
                float a0, a1; upk2(acc, a0, a1);
                const float s = (a0 + a1) * 0.35355339059327373f;
                sc[tt] = s; mx = fmaxf(mx, s);
            }
            float sum = 0.f;
#pragma unroll
            for (int tt = 0; tt < 9; tt++) { sc[tt] = __expf(sc[tt] - mx); sum += sc[tt]; }
            const float inv = __fdividef(1.0f, sum);
            ull vacc[4] = {0ull, 0ull, 0ull, 0ull};
#pragma unroll
            for (int tt = 0; tt < 9; tt++) {
                const ull s2 = dup2(sc[tt]);
                const ull* vr = (const ull*)&s_v[(rb + tt) * KSTR];
#pragma unroll
                for (int p = 0; p < 4; p++) vacc[p] = fma2(s2, vr[h*4 + p], vacc[p]);
            }
#pragma unroll
            for (int p = 0; p < 4; p++) {
                float a0, a1; upk2(vacc[p], a0, a1);
                ao[tok][h*8 + 2*p] = a0 * inv; ao[tok][h*8 + 2*p + 1] = a1 * inv;
            }
        }
    }

    // ---- out projection, JOINT over 2 tokens (out_w loaded once) ----
    ull op[2][8];
    {
        const ull* bp = (const ull*)w.out_b;
#pragma unroll
        for (int p = 0; p < 8; p++) { op[0][p] = bp[p]; op[1][p] = bp[p]; }
#pragma unroll
        for (int k = 0; k < 16; k++) {
            const ull wk = c_w64[CB_OUTW + k*8];   // note: row base; per-p below
            (void)wk;
            const ull v0 = dup2(ao[0][k]), v1 = dup2(ao[1][k]);
#pragma unroll
            for (int p = 0; p < 8; p++) {
                const ull ww_ = c_w64[CB_OUTW + k*8 + p];
                op[0][p] = fma2(v0, ww_, op[0][p]);
                op[1][p] = fma2(v1, ww_, op[1][p]);
            }
        }
    }
    __syncthreads();                                         // S2: K/V reads done

    // ---- reconstruct x per token, add out-proj, LN, store to s_x ----
#pragma unroll
    for (int tok = 0; tok < 2; tok++) {
        const ull dnd = dup2(dn_[tok]), snd = dup2(sn_[tok]), rr = dup2(rr_[tok]);
        const ull *A = (const ull*)w.xga, *B = (const ull*)w.xgb,
                  *C = (const ull*)w.xgc, *N = (const ull*)w.n1b;
        float x[16];
#pragma unroll
        for (int p = 0; p < 8; p++) {
            ull v = fma2(rr, fma2(dnd, A[p], fma2(snd, B[p], C[p])), N[p]);
            float f0, f1; upk2(v, f0, f1);
            float g0_, g1_; upk2(op[tok][p], g0_, g1_);
            x[2*p] = f0 + g0_; x[2*p+1] = f1 + g1_;
        }
        ln16(x, w.n1g, w.n1b);
        const int row = tok ? rowB : rowA;
#pragma unroll
        for (int j = 0; j < 16; j++) s_x[row * KSTR + j] = x[j];
    }
    __syncthreads();                                         // S3

    // ---- gate: cooperative stats over both patch sets ----
#pragma unroll
    for (int tok = 0; tok < 2; tok++) {
        const int pp = pl + tok * 32;
        const int rb = tok * 288 + pbrow;
#pragma unroll
        for (int cc = 0; cc < 2; cc++) {
            const int c = (cc == 0) ? t : (9 + t);
            if (cc == 0 || t < 7) {
                float vals[9]; float m = 0.f, mxv = -1e30f;
#pragma unroll
                for (int tt = 0; tt < 9; tt++) {
                    const float v = s_x[(rb + tt) * KSTR + c];
                    vals[tt] = v; m += v; mxv = fmaxf(mxv, v);
                }
                m *= (1.0f / 9.0f);
                float var = 0.f;
#pragma unroll
                for (int tt = 0; tt < 9; tt++) { const float d = vals[tt] - m; var = fmaf(d, d, var); }
                const float sd = sqrtf(var * 0.125f);
                s_st[pp*48 + c] = m; s_st[pp*48 + 16 + c] = mxv; s_st[pp*48 + 32 + c] = sd;
            }
        }
    }
    __syncthreads();                                         // S4

    if (t < 8) {
#pragma unroll
        for (int tok = 0; tok < 2; tok++) {
            const int pp = pl + tok * 32;
            const ull* stp = (const ull*)&s_st[pp * 48];
#pragma unroll
            for (int cc = 0; cc < 2; cc++) {
                const int i = (cc == 0) ? t : (8 + t);
                const ull* wr = (const ull*)&w.gw1t[i * 48];
                ull acc = 0ull;
#pragma unroll
                for (int p = 0; p < 24; p++) acc = fma2(stp[p], wr[p], acc);
                float a0, a1; upk2(acc, a0, a1);
                s_hid[pp*16 + i] = gelu_fast(a0 + a1 + w.gb1[i]);
            }
        }
    }
    __syncthreads();                                         // S5

    // logits + softmax per token (gw2 on constant port)
    float g_[2][3];
#pragma unroll
    for (int tok = 0; tok < 2; tok++) {
        const int pp = pl + tok * 32;
        const float* cw2 = (const float*)&c_w64[CB_GW2];
        const float* hv = &s_hid[pp * 16];
        float lg0 = w.gb2[0], lg1 = w.gb2[1], lg2 = w.gb2[2];
#pragma unroll
        for (int i = 0; i < 16; i++) {
            const float h = hv[i];
            lg0 = fmaf(h, cw2[i*3 + 0], lg0);
            lg1 = fmaf(h, cw2[i*3 + 1], lg1);
            lg2 = fmaf(h, cw2[i*3 + 2], lg2);
        }
        const float mxl = fmaxf(lg0, fmaxf(lg1, lg2));
        const float e0 = __expf(lg0 - mxl), e1 = __expf(lg1 - mxl), e2 = __expf(lg2 - mxl);
        const float inv = __fdividef(1.0f, e0 + e1 + e2);
        g_[tok][0] = e0 * inv; g_[tok][1] = e1 * inv; g_[tok][2] = e2 * inv;
    }
    if (t == 0) {
        atomicAdd(&s_gate[0], (double)g_[0][0] + (double)g_[1][0]);
        atomicAdd(&s_gate[1], (double)g_[0][1] + (double)g_[1][1]);
        atomicAdd(&s_gate[2], (double)g_[0][2] + (double)g_[1][2]);
    }

    // ---- experts: JOINT 2-token, W1/W2 on constant port (loaded once) ----
    const int rx0 = rowA * KSTR, rx1 = rowB * KSTR;
    const ull dnd0 = dup2(dn_[0]), snd0 = dup2(sn_[0]);
    const ull dnd1 = dup2(dn_[1]), snd1 = dup2(sn_[1]);
    ull moe0[8], moe1[8];
    {
        const ull *bg = (const ull*)w.b2g, *bs = (const ull*)w.b2s, *bf = (const ull*)w.b2f;
        const ull a0 = dup2(g_[0][0]), b0 = dup2(g_[0][1]), c0 = dup2(g_[0][2]);
        const ull a1 = dup2(g_[1][0]), b1 = dup2(g_[1][1]), c1 = dup2(g_[1][2]);
#pragma unroll
        for (int p = 0; p < 8; p++) {
            moe0[p] = fma2(a0, bg[p], fma2(b0, bs[p], fma2(c0, bf[p], 0ull)));
            moe1[p] = fma2(a1, bg[p], fma2(b1, bs[p], fma2(c1, bf[p], 0ull)));
        }
    }

#define EXPERT_C2(B1, B2, AA, BB, CC, E) {                                \
        ull h0[8], h1[8];                                                 \
        {                                                                 \
            const ull *Ap = (const ull*)(AA), *Bp = (const ull*)(BB),     \
                      *Cp = (const ull*)(CC);                             \
            _Pragma("unroll") for (int p = 0; p < 8; p++) {               \
                const ull Av = Ap[p], Bv = Bp[p], Cv = Cp[p];             \
                h0[p] = fma2(dnd0, Av, fma2(snd0, Bv, Cv));               \
                h1[p] = fma2(dnd1, Av, fma2(snd1, Bv, Cv));               \
            }                                                             \
        }                                                                 \
        _Pragma("unroll") for (int k = 0; k < 16; k++) {                  \
            const ull xv0 = dup2(s_x[rx0 + k]);                           \
            const ull xv1 = dup2(s_x[rx1 + k]);                           \
            _Pragma("unroll") for (int p = 0; p < 8; p++) {               \
                const ull wk = c_w64[(B1) + k*8 + p];                     \
                h0[p] = fma2(xv0, wk, h0[p]);                             \
                h1[p] = fma2(xv1, wk, h1[p]);                             \
            }                                                             \
        }                                                                 \
        float hf0[16], hf1[16];                                           \
        const float ge0 = g_[0][E], ge1 = g_[1][E];                       \
        _Pragma("unroll") for (int p = 0; p < 8; p++) {                   \
            float a0_, a1_;                                               \
            upk2(h0[p], a0_, a1_);                                        \
            hf0[2*p] = gelu_fast(a0_) * ge0; hf0[2*p+1] = gelu_fast(a1_) * ge0; \
            upk2(h1[p], a0_, a1_);                                        \
            hf1[2*p] = gelu_fast(a0_) * ge1; hf1[2*p+1] = gelu_fast(a1_) * ge1; \
        }                                                                 \
        _Pragma("unroll") for (int k = 0; k < 16; k++) {                  \
            const ull v0 = dup2(hf0[k]);                                  \
            const ull v1 = dup2(hf1[k]);                                  \
            _Pragma("unroll") for (int p = 0; p < 8; p++) {               \
                const ull wk = c_w64[(B2) + k*8 + p];                     \
                moe0[p] = fma2(v0, wk, moe0[p]);                          \
                moe1[p] = fma2(v1, wk, moe1[p]);                          \
            }                                                             \
        }                                                                 \
    }

    EXPERT_C2(CB_EG1, CB_EG2, w.Ag, w.Bg, w.Cg, 0)
    EXPERT_C2(CB_ES1, CB_ES2, w.As, w.Bs, w.Cs, 1)
    EXPERT_C2(CB_EF1, CB_EF2, w.Af, w.Bf, w.Cf, 2)
#undef EXPERT_C2

    // ---- final per token: residual folds + LN + project + sigmoid ----
#pragma unroll
    for (int tok = 0; tok < 2; tok++) {
        const int rx = tok ? rx1 : rx0;
        const ull* xr = (const ull*)&s_x[rx];
        const ull* mo = tok ? moe1 : moe0;
        const ull two = dup2(2.0f);
        const ull gdp = dup2(g_[tok][0] + g_[tok][2]);
        const ull gsp = dup2(g_[tok][1] + g_[tok][2]);
        const ull dnd = dup2(dn_[tok]), snd = dup2(sn_[tok]);
        const ull *dw = (const ull*)w.dpw, *db = (const ull*)w.dpb;
        const ull *sw = (const ull*)w.spw, *sb = (const ull*)w.spb;
        float mf[16];
#pragma unroll
        for (int p = 0; p < 8; p++) {
            ull v = fma2(two, xr[p], mo[p]);
            const ull dpf = fma2(dnd, dw[p], db[p]);
            const ull spf = fma2(snd, sw[p], sb[p]);
            v = fma2(gdp, dpf, v);
            v = fma2(gsp, spf, v);
            upk2(v, mf[2*p], mf[2*p+1]);
        }
        ln16(mf, w.n2g, w.n2b);
        const float* cpw = (const float*)&c_w64[CB_PW];
        float z = w.pb[0];
#pragma unroll
        for (int j = 0; j < 16; j++) z = fmaf(mf[j], cpw[j], z);
        out[pix_[tok]] = __fdividef(1.0f, 1.0f + __expf(-z));
    }

    __syncthreads();                                         // S6
    if (tid < 3) atomicAdd(&g_gate_acc[tid], s_gate[tid]);
}

__global__ void tail_kernel(float* __restrict__ out) {
    if (threadIdx.x < 3)
        out[NPIX + threadIdx.x] = (float)(g_gate_acc[threadIdx.x] / (double)NPATCH);
}

// ---------------- launch ----------------
extern "C" void kernel_launch(void* const* d_in, const int* in_sizes, int n_in,
                              void* d_out, int out_size) {
    Ptrs ptrs;
    for (int i = 0; i < 32; i++) ptrs.p[i] = (const float*)d_in[i];
    const float* depth = (const float*)d_in[0];
    const float* sem   = (const float*)d_in[1];
    float* out = (float*)d_out;

    cudaFuncSetAttribute(moe_kernel, cudaFuncAttributeMaxDynamicSharedMemorySize, SMEM_TOTAL);

    // populate constant weights from inputs (graph-capturable async D2D)
    void* caddr = nullptr;
    cudaGetSymbolAddress(&caddr, c_w64);
    cudaMemcpyAsync((char*)caddr + CB_EG1*8,  d_in[12], 1024, cudaMemcpyDeviceToDevice);
    cudaMemcpyAsync((char*)caddr + CB_EG2*8,  d_in[14], 1024, cudaMemcpyDeviceToDevice);
    cudaMemcpyAsync((char*)caddr + CB_ES1*8,  d_in[16], 1024, cudaMemcpyDeviceToDevice);
    cudaMemcpyAsync((char*)caddr + CB_ES2*8,  d_in[18], 1024, cudaMemcpyDeviceToDevice);
    cudaMemcpyAsync((char*)caddr + CB_EF1*8,  d_in[20], 1024, cudaMemcpyDeviceToDevice);
    cudaMemcpyAsync((char*)caddr + CB_EF2*8,  d_in[22], 1024, cudaMemcpyDeviceToDevice);
    cudaMemcpyAsync((char*)caddr + CB_OUTW*8, d_in[8],  1024, cudaMemcpyDeviceToDevice);
    cudaMemcpyAsync((char*)caddr + CB_GW2*8,  d_in[28], 192,  cudaMemcpyDeviceToDevice);
    cudaMemcpyAsync((char*)caddr + CB_PW*8,   d_in[30], 64,   cudaMemcpyDeviceToDevice);

    pack_kernel<<<1, 256>>>(ptrs);

    void* gaddr = nullptr;
    cudaGetSymbolAddress(&gaddr, g_wblob);
    cudaMemcpyAsync((char*)caddr + CB_QA*8, gaddr, 768, cudaMemcpyDeviceToDevice);

    semprob_kernel<<<NPIX / 4 / 256, 256>>>(sem, depth);
    finalize_kernel<<<1, 32>>>();
    moe_kernel<<<NPATCH / PPB, TPB, SMEM_TOTAL>>>(depth, out);
    tail_kernel<<<1, 32>>>(out);
}

// round 17
// speedup vs baseline: 1.1853x; 1.0603x over previous
#include <cuda_runtime.h>
#include <math.h>

// ---------------- problem constants ----------------
#define HH 480
#define WW2 480
#define HXW (HH*WW2)            // 230400
#define BATCH 8
#define NPIX (BATCH*HXW)        // 1843200
#define NCH 19
#define GRID_P 160
#define NPATCH (BATCH*GRID_P*GRID_P)   // 204800
#define PPB 64                  // patches per block (2 tokens per thread)
#define TPB 288                 // threads
#define NROWS (PPB*9)           // 576 rows
#define KSTR 18                 // s_x row stride (floats)

typedef unsigned long long ull;

// ---------------- f32x2 helpers ----------------
__device__ __forceinline__ ull dup2(float a) {
    ull r; asm("mov.b64 %0, {%1,%1};" : "=l"(r) : "f"(a)); return r;
}
__device__ __forceinline__ void upk2(ull v, float& a, float& b) {
    asm("mov.b64 {%0,%1}, %2;" : "=f"(a), "=f"(b) : "l"(v));
}
__device__ __forceinline__ ull fma2(ull a, ull b, ull c) {
    ull d; asm("fma.rn.f32x2 %0, %1, %2, %3;" : "=l"(d) : "l"(a), "l"(b), "l"(c)); return d;
}

// ---------------- device scratch ----------------
__device__ float  g_semprob[NPIX];
__device__ double g_acc[BATCH][4];
__device__ double g_gate_acc[3];
__device__ float4 g_norm[BATCH];

// Broadcast weights on the CONSTANT port (8 KB bank; some holes unused).
__constant__ ull c_w64[1024];
#define CB_EG1 0
#define CB_EG2 128
#define CB_ES1 256
#define CB_ES2 384
#define CB_EF1 512
#define CB_EF2 640
#define CB_WC0 768          // 6 vectors x 8 ull (Wc_h rows 0..2, both heads)
#define CB_XB0 816          // 8 ull  (out_b + n1b + Wc row-3 folds)
#define CB_MH  824          // 16 ull = 32 floats (M_h 4x4 x 2 heads)
#define CB_GW2 992
#define CB_PW 1016

// ---------------- packed weights (smem-resident part) ----------------
// Head: wcx/xb0/Mh are written by pack_kernel phase 2, then D2D'd to constant.
struct SW {
    float wcx[96]; float xb0[16]; float Mh[32];     // 144 floats (D2D -> constant)
    float qa[48]; float qb[48]; float qc[48]; float qd[48];
    float out_b[16];
    float Ag[16]; float Bg[16]; float Cg[16];
    float As[16]; float Bs[16]; float Cs[16];
    float Af[16]; float Bf[16]; float Cf[16];
    float b2g[16]; float b2s[16]; float b2f[16];
    float gw1t[768]; float gb1[16]; float gb2[4];
    float pb[4];
    float dpw[16]; float dpb[16]; float spw[16]; float spb[16];
    float xga[16]; float xgb[16]; float xgc[16];
    float mst[8];
    float n1g[16]; float n1b[16]; float n2g[16]; float n2b[16];
};
#define NWFLOATS ((int)(sizeof(SW)/4))
__device__ float g_wblob[sizeof(SW)/4];

struct Ptrs { const float* p[32]; };

// dynamic smem layout (no overlays; plenty of room at 2 blocks/SM)
#define SW_BYTES ((int)sizeof(SW))
#define SU_OFF   SW_BYTES
#define SU_BYTES (NROWS*16)                   // 9216: u rows as float4
#define SX_OFF   (SU_OFF + SU_BYTES)
#define SX_BYTES (NROWS*KSTR*4)               // 41472
#define SST_OFF  (SX_OFF + SX_BYTES)          // [64][48]
#define SHID_OFF (SST_OFF + 64*48*4)          // [64][16]
#define SGATE_OFF (SHID_OFF + 64*16*4)
#define SMEM_TOTAL (SGATE_OFF + 32)

// ---------------- pack weights + precompute folds ----------------
__global__ void pack_kernel(Ptrs in) {
    SW* w = (SW*)g_wblob;
    const int tid = threadIdx.x, nt = blockDim.x;
#define CP(dst, idx, n) for (int i = tid; i < (n); i += nt) (dst)[i] = in.p[idx][i];
    CP(w->out_b, 9, 16)
    CP(w->b2g, 15, 16)   CP(w->b2s, 19, 16)  CP(w->b2f, 23, 16)
    CP(w->gb1, 27, 16)
    CP(w->dpw, 2, 16) CP(w->dpb, 3, 16) CP(w->spw, 4, 16) CP(w->spb, 5, 16)
    CP(w->n1g, 10, 16) CP(w->n1b, 11, 16) CP(w->n2g, 24, 16) CP(w->n2b, 25, 16)
#undef CP
    for (int i = tid; i < 768; i += nt) {         // g_w1 [48,16] -> gw1t [16][48]
        int r = i / 48, s = i - r * 48;
        w->gw1t[i] = in.p[26][s * 16 + r];
    }
    double abar = 0, bbar = 0, cbar = 0;
    for (int k = 0; k < 16; k++) {
        abar += in.p[2][k]; bbar += in.p[4][k];
        cbar += (double)in.p[3][k] + in.p[5][k];
    }
    abar /= 16.0; bbar /= 16.0; cbar /= 16.0;

    if (tid < 48) {                               // rank-2 qkv fold columns
        const int o = tid;
        double pa = 0, pb = 0, pc = 0, pd = in.p[7][o];
        for (int j = 0; j < 16; j++) {
            const double a0 = in.p[2][j] - abar;
            const double b0 = in.p[4][j] - bbar;
            const double c0 = ((double)in.p[3][j] + in.p[5][j]) - cbar;
            const double g = in.p[10][j];
            const double wv = in.p[6][j * 48 + o];
            pa += a0 * g * wv; pb += b0 * g * wv; pc += c0 * g * wv;
            pd += (double)in.p[11][j] * wv;
        }
        w->qa[o] = (float)pa; w->qb[o] = (float)pb;
        w->qc[o] = (float)pc; w->qd[o] = (float)pd;
    }
    if (tid >= 64 && tid < 80) {
        const int j = tid - 64;
        const double a0 = in.p[2][j] - abar;
        const double b0 = in.p[4][j] - bbar;
        const double c0 = ((double)in.p[3][j] + in.p[5][j]) - cbar;
        const double g = in.p[10][j];
        w->xga[j] = (float)(a0 * g); w->xgb[j] = (float)(b0 * g); w->xgc[j] = (float)(c0 * g);
    }
    if (tid == 96) {
        double maa = 0, mab = 0, mbb = 0, mac = 0, mbc = 0, mcc = 0;
        for (int j = 0; j < 16; j++) {
            const double a0 = in.p[2][j] - abar;
            const double b0 = in.p[4][j] - bbar;
            const double c0 = ((double)in.p[3][j] + in.p[5][j]) - cbar;
            maa += a0*a0; mab += a0*b0; mbb += b0*b0;
            mac += a0*c0; mbc += b0*c0; mcc += c0*c0;
        }
        w->mst[0] = (float)(maa/16.0); w->mst[1] = (float)(mab/16.0);
        w->mst[2] = (float)(mbb/16.0); w->mst[3] = (float)(mac/16.0);
        w->mst[4] = (float)(mbc/16.0); w->mst[5] = (float)(mcc/16.0);
        w->mst[6] = 0.f; w->mst[7] = 0.f;
    }
    if (tid >= 160 && tid < 176) {
        const int j = tid - 160;
        float ag = 0, cg = 0, bs = 0, cs = 0, af = 0, bf = 0, cf = 0;
        for (int k = 0; k < 16; k++) {
            const float eg = in.p[12][k*16 + j], es = in.p[16][k*16 + j], ef = in.p[20][k*16 + j];
            const float dpwk = in.p[2][k], dpbk = in.p[3][k];
            const float spwk = in.p[4][k], spbk = in.p[5][k];
            ag += dpwk * eg;  cg += dpbk * eg;
            bs += spwk * es;  cs += spbk * es;
            af += dpwk * ef;  bf += spwk * ef;
            cf += (dpbk + spbk) * ef;
        }
        w->Ag[j] = ag; w->Bg[j] = 0.f; w->Cg[j] = cg + in.p[13][j];
        w->As[j] = 0.f; w->Bs[j] = bs; w->Cs[j] = cs + in.p[17][j];
        w->Af[j] = af; w->Bf[j] = bf; w->Cf[j] = cf + in.p[21][j];
    }
    if (tid >= 176 && tid < 179) w->gb2[tid-176] = in.p[29][tid-176];
    if (tid == 179) w->gb2[3] = 0.f;
    if (tid == 180) w->pb[0] = in.p[31][0];
    if (tid < BATCH*4) ((double*)g_acc)[tid] = 0.0;
    if (tid >= 60 && tid < 63) g_gate_acc[tid-60] = 0.0;

    __syncthreads();
    // ---- phase 2: bilinear attention folds from qa..qd ----
#define QCOL(c, row) ((c)==0 ? w->qa[row] : (c)==1 ? w->qb[row] : (c)==2 ? w->qc[row] : w->qd[row])
    if (tid < 32) {                 // Mh[h*16 + c*4 + l] = (Q_h^T K_h / sqrt8)[c][l]
        const int h = tid >> 4, c = (tid >> 2) & 3, l = tid & 3;
        float acc = 0.f;
        for (int e = 0; e < 8; e++)
            acc += QCOL(c, h*8 + e) * QCOL(l, 16 + h*8 + e);
        w->Mh[tid] = acc * 0.35355339059327373f;
    }
    if (tid >= 32 && tid < 128) {   // wcx[(h*3+l)*16 + o] = (V_h^T out_w_h)[l][o], l=0..2
        const int idx = tid - 32;
        const int h = idx / 48, rem2 = idx - h*48, l = rem2 / 16, o = rem2 - l*16;
        float acc = 0.f;
        for (int e = 0; e < 8; e++)
            acc += QCOL(l, 32 + h*8 + e) * in.p[8][(h*8 + e)*16 + o];
        w->wcx[(h*3 + l)*16 + o] = acc;
    }
    if (tid >= 128 && tid < 144) {  // xb0 = out_b + n1b + Wc row-3 folds (s3 == 1)
        const int o = tid - 128;
        float acc = in.p[9][o] + in.p[11][o];
        for (int h = 0; h < 2; h++)
            for (int e = 0; e < 8; e++)
                acc += QCOL(3, 32 + h*8 + e) * in.p[8][(h*8 + e)*16 + o];
        w->xb0[o] = acc;
    }
#undef QCOL
}

// ---------------- stage 1 ----------------
__global__ void semprob_kernel(const float* __restrict__ sem,
                               const float* __restrict__ depth) {
    const int q = blockIdx.x * 256 + threadIdx.x;
    const int p4 = q * 4;
    const int b = p4 / HXW;
    const int ip = p4 - b * HXW;
    const float4* base = (const float4*)(sem + (long)b * NCH * HXW + ip);
    float4 v[NCH];
#pragma unroll
    for (int c = 0; c < NCH; c++) v[c] = __ldg(base + (long)c * (HXW/4));
    float4 mx = v[0];
#pragma unroll
    for (int c = 1; c < NCH; c++) {
        mx.x = fmaxf(mx.x, v[c].x); mx.y = fmaxf(mx.y, v[c].y);
        mx.z = fmaxf(mx.z, v[c].z); mx.w = fmaxf(mx.w, v[c].w);
    }
    float4 sum = make_float4(0.f, 0.f, 0.f, 0.f);
#pragma unroll
    for (int c = 0; c < NCH; c++) {
        sum.x += __expf(v[c].x - mx.x); sum.y += __expf(v[c].y - mx.y);
        sum.z += __expf(v[c].z - mx.z); sum.w += __expf(v[c].w - mx.w);
    }
    float4 prob;
    prob.x = __fdividef(1.0f, sum.x); prob.y = __fdividef(1.0f, sum.y);
    prob.z = __fdividef(1.0f, sum.z); prob.w = __fdividef(1.0f, sum.w);
    ((float4*)g_semprob)[q] = prob;
    const float4 d = __ldg((const float4*)depth + q);

    double rd  = (double)d.x + (double)d.y + (double)d.z + (double)d.w;
    double rd2 = (double)d.x*d.x + (double)d.y*d.y + (double)d.z*d.z + (double)d.w*d.w;
    double rs  = (double)prob.x + (double)prob.y + (double)prob.z + (double)prob.w;
    double rs2 = (double)prob.x*prob.x + (double)prob.y*prob.y
               + (double)prob.z*prob.z + (double)prob.w*prob.w;
#pragma unroll
    for (int off = 16; off > 0; off >>= 1) {
        rd  += __shfl_down_sync(0xffffffffu, rd,  off);
        rd2 += __shfl_down_sync(0xffffffffu, rd2, off);
        rs  += __shfl_down_sync(0xffffffffu, rs,  off);
        rs2 += __shfl_down_sync(0xffffffffu, rs2, off);
    }
    __shared__ double sp[8][4];
    const int lane = threadIdx.x & 31, wid = threadIdx.x >> 5;
    if (lane == 0) { sp[wid][0] = rd; sp[wid][1] = rd2; sp[wid][2] = rs; sp[wid][3] = rs2; }
    __syncthreads();
    if (threadIdx.x == 0) {
        double a0 = 0, a1 = 0, a2 = 0, a3 = 0;
        for (int i = 0; i < 8; i++) { a0 += sp[i][0]; a1 += sp[i][1]; a2 += sp[i][2]; a3 += sp[i][3]; }
        atomicAdd(&g_acc[b][0], a0); atomicAdd(&g_acc[b][1], a1);
        atomicAdd(&g_acc[b][2], a2); atomicAdd(&g_acc[b][3], a3);
    }
}

__global__ void finalize_kernel() {
    const int b = threadIdx.x;
    if (b < BATCH) {
        const double n = (double)HXW;
        double md = g_acc[b][0] / n;
        double vd = (g_acc[b][1] - n * md * md) / (n - 1.0);
        double ms = g_acc[b][2] / n;
        double vs = (g_acc[b][3] - n * ms * ms) / (n - 1.0);
        g_norm[b] = make_float4((float)md, (float)(1.0 / (sqrt(vd) + 1e-6)),
                                (float)ms, (float)(1.0 / (sqrt(vs) + 1e-6)));
    }
}

// ---------------- stage 2 helpers ----------------
__device__ __forceinline__ void ln16(float* x, const float* g, const float* b) {
    float m = 0.f;
#pragma unroll
    for (int j = 0; j < 16; j++) m += x[j];
    m *= 0.0625f;
    float v = 0.f;
#pragma unroll
    for (int j = 0; j < 16; j++) { float d = x[j] - m; v = fmaf(d, d, v); }
    v *= 0.0625f;
    const float r = rsqrtf(v + 1e-5f);
#pragma unroll
    for (int j = 0; j < 16; j++) x[j] = (x[j] - m) * r * g[j] + b[j];
}

// gelu via HW tanh (MUFU.TANH)
__device__ __forceinline__ float gelu_fast(float x) {
    const float g = 0.7978845608028654f * fmaf(0.044715f * x, x * x, x);
    float th;
    asm("tanh.approx.f32 %0, %1;" : "=f"(th) : "f"(g));
    return 0.5f * x * (1.0f + th);
}

// ---------------- stage 2: per-patch transformer/MoE (2 tokens/thread) ----------------
__global__ void __launch_bounds__(TPB, 2)
moe_kernel(const float* __restrict__ depth, float* __restrict__ out) {
    extern __shared__ __align__(16) unsigned char dsm[];
    SW& w = *(SW*)dsm;
    float4* s_u = (float4*)(dsm + SU_OFF);    // [576] u rows
    float* s_x = (float*)(dsm + SX_OFF);      // [576][KSTR]
    float* s_st = (float*)(dsm + SST_OFF);    // [64][48]
    float* s_hid = (float*)(dsm + SHID_OFF);  // [64][16]
    double* s_gate = (double*)(dsm + SGATE_OFF);

    const int tid = threadIdx.x;
    for (int i = tid; i < NWFLOATS; i += TPB) ((float*)&w)[i] = g_wblob[i];
    if (tid < 3) s_gate[tid] = 0.0;
    __syncthreads();                                         // S0

    const int pl = tid / 9;
    const int t = tid - pl * 9;
    const int pbrow = tid - t;                 // = pl*9
    const int rowA = tid, rowB = tid + 288;

    float dn_[2], sn_[2], rr_[2];
    int pix_[2];
#pragma unroll
    for (int tok = 0; tok < 2; tok++) {
        const int P = blockIdx.x * PPB + pl + tok * 32;
        const int b = P / (GRID_P * GRID_P);
        const int rem = P - b * (GRID_P * GRID_P);
        const int hh = rem / GRID_P, ww = rem - hh * GRID_P;
        const int py = hh * 3 + t / 3, px = ww * 3 + (t % 3);
        const int pix = (b * HH + py) * WW2 + px;
        pix_[tok] = pix;
        const float4 nm = g_norm[b];
        const float dn = (depth[pix] - nm.x) * nm.y;
        const float sn = (g_semprob[pix] - nm.z) * nm.w;
        dn_[tok] = dn; sn_[tok] = sn;
        const float var = w.mst[0]*dn*dn + 2.f*w.mst[1]*dn*sn + w.mst[2]*sn*sn
                        + 2.f*w.mst[3]*dn + 2.f*w.mst[4]*sn + w.mst[5];
        rr_[tok] = rsqrtf(var + 1e-5f);
    }

    // ---- store u features (that's the whole "qkv" now) ----
    s_u[rowA] = make_float4(rr_[0]*dn_[0], rr_[0]*sn_[0], rr_[0], 1.f);
    s_u[rowB] = make_float4(rr_[1]*dn_[1], rr_[1]*sn_[1], rr_[1], 1.f);
    __syncthreads();                                         // S1

    // ---- bilinear attention + folded out-proj + LN, per token ----
    const float* cM = (const float*)&c_w64[CB_MH];
#pragma unroll
    for (int tok = 0; tok < 2; tok++) {
        const int rb = pbrow + tok * 288;
        const float u0 = rr_[tok]*dn_[tok], u1 = rr_[tok]*sn_[tok], u2 = rr_[tok];
        float m0[4], m1[4];
#pragma unroll
        for (int l = 0; l < 4; l++) {
            m0[l] = fmaf(u0, cM[l],      fmaf(u1, cM[4+l],  fmaf(u2, cM[8+l],  cM[12+l])));
            m1[l] = fmaf(u0, cM[16+l],   fmaf(u1, cM[20+l], fmaf(u2, cM[24+l], cM[28+l])));
        }
        float sc0[9], sc1[9]; float mx0 = -1e30f, mx1 = -1e30f;
#pragma unroll
        for (int tt = 0; tt < 9; tt++) {
            const float4 uj = s_u[rb + tt];
            const float a = fmaf(m0[0], uj.x, fmaf(m0[1], uj.y, fmaf(m0[2], uj.z, m0[3])));
            const float c = fmaf(m1[0], uj.x, fmaf(m1[1], uj.y, fmaf(m1[2], uj.z, m1[3])));
            sc0[tt] = a; sc1[tt] = c;
            mx0 = fmaxf(mx0, a); mx1 = fmaxf(mx1, c);
        }
        float sum0 = 0.f, sum1 = 0.f;
#pragma unroll
        for (int tt = 0; tt < 9; tt++) {
            sc0[tt] = __expf(sc0[tt] - mx0); sum0 += sc0[tt];
            sc1[tt] = __expf(sc1[tt] - mx1); sum1 += sc1[tt];
        }
        float a00 = 0.f, a01 = 0.f, a02 = 0.f, a10 = 0.f, a11 = 0.f, a12 = 0.f;
#pragma unroll
        for (int tt = 0; tt < 9; tt++) {
            const float4 uj = s_u[rb + tt];
            a00 = fmaf(sc0[tt], uj.x, a00); a01 = fmaf(sc0[tt], uj.y, a01); a02 = fmaf(sc0[tt], uj.z, a02);
            a10 = fmaf(sc1[tt], uj.x, a10); a11 = fmaf(sc1[tt], uj.y, a11); a12 = fmaf(sc1[tt], uj.z, a12);
        }
        const float inv0 = __fdividef(1.f, sum0), inv1 = __fdividef(1.f, sum1);
        const ull s00 = dup2(a00*inv0), s01 = dup2(a01*inv0), s02 = dup2(a02*inv0);
        const ull s10 = dup2(a10*inv1), s11 = dup2(a11*inv1), s12 = dup2(a12*inv1);

        const ull dnd = dup2(dn_[tok]), snd = dup2(sn_[tok]), rr = dup2(rr_[tok]);
        const ull *A = (const ull*)w.xga, *B = (const ull*)w.xgb, *C = (const ull*)w.xgc;
        float x[16];
#pragma unroll
        for (int p = 0; p < 8; p++) {
            ull v = c_w64[CB_XB0 + p];
            v = fma2(s00, c_w64[CB_WC0 +      p], v);
            v = fma2(s01, c_w64[CB_WC0 +  8 + p], v);
            v = fma2(s02, c_w64[CB_WC0 + 16 + p], v);
            v = fma2(s10, c_w64[CB_WC0 + 24 + p], v);
            v = fma2(s11, c_w64[CB_WC0 + 32 + p], v);
            v = fma2(s12, c_w64[CB_WC0 + 40 + p], v);
            v = fma2(rr, fma2(dnd, A[p], fma2(snd, B[p], C[p])), v);
            upk2(v, x[2*p], x[2*p+1]);
        }
        ln16(x, w.n1g, w.n1b);
        const int row = tok ? rowB : rowA;
#pragma unroll
        for (int j = 0; j < 16; j++) s_x[row * KSTR + j] = x[j];
    }
    __syncthreads();                                         // S3

    // ---- gate: cooperative stats over both patch sets ----
#pragma unroll
    for (int tok = 0; tok < 2; tok++) {
        const int pp = pl + tok * 32;
        const int rb = tok * 288 + pbrow;
#pragma unroll
        for (int cc = 0; cc < 2; cc++) {
            const int c = (cc == 0) ? t : (9 + t);
            if (cc == 0 || t < 7) {
                float vals[9]; float m = 0.f, mxv = -1e30f;
#pragma unroll
                for (int tt = 0; tt < 9; tt++) {
                    const float v = s_x[(rb + tt) * KSTR + c];
                    vals[tt] = v; m += v; mxv = fmaxf(mxv, v);
                }
                m *= (1.0f / 9.0f);
                float var = 0.f;
#pragma unroll
                for (int tt = 0; tt < 9; tt++) { const float d = vals[tt] - m; var = fmaf(d, d, var); }
                const float sd = sqrtf(var * 0.125f);
                s_st[pp*48 + c] = m; s_st[pp*48 + 16 + c] = mxv; s_st[pp*48 + 32 + c] = sd;
            }
        }
    }
    __syncthreads();                                         // S4

    if (t < 8) {
#pragma unroll
        for (int tok = 0; tok < 2; tok++) {
            const int pp = pl + tok * 32;
            const ull* stp = (const ull*)&s_st[pp * 48];
#pragma unroll
            for (int cc = 0; cc < 2; cc++) {
                const int i = (cc == 0) ? t : (8 + t);
                const ull* wr = (const ull*)&w.gw1t[i * 48];
                ull acc = 0ull;
#pragma unroll
                for (int p = 0; p < 24; p++) acc = fma2(stp[p], wr[p], acc);
                float a0, a1; upk2(acc, a0, a1);
                s_hid[pp*16 + i] = gelu_fast(a0 + a1 + w.gb1[i]);
            }
        }
    }
    __syncthreads();                                         // S5

    // logits + softmax per token (gw2 on constant port)
    float g_[2][3];
#pragma unroll
    for (int tok = 0; tok < 2; tok++) {
        const int pp = pl + tok * 32;
        const float* cw2 = (const float*)&c_w64[CB_GW2];
        const float* hv = &s_hid[pp * 16];
        float lg0 = w.gb2[0], lg1 = w.gb2[1], lg2 = w.gb2[2];
#pragma unroll
        for (int i = 0; i < 16; i++) {
            const float h = hv[i];
            lg0 = fmaf(h, cw2[i*3 + 0], lg0);
            lg1 = fmaf(h, cw2[i*3 + 1], lg1);
            lg2 = fmaf(h, cw2[i*3 + 2], lg2);
        }
        const float mxl = fmaxf(lg0, fmaxf(lg1, lg2));
        const float e0 = __expf(lg0 - mxl), e1 = __expf(lg1 - mxl), e2 = __expf(lg2 - mxl);
        const float inv = __fdividef(1.0f, e0 + e1 + e2);
        g_[tok][0] = e0 * inv; g_[tok][1] = e1 * inv; g_[tok][2] = e2 * inv;
    }
    if (t == 0) {
        atomicAdd(&s_gate[0], (double)g_[0][0] + (double)g_[1][0]);
        atomicAdd(&s_gate[1], (double)g_[0][1] + (double)g_[1][1]);
        atomicAdd(&s_gate[2], (double)g_[0][2] + (double)g_[1][2]);
    }

    // ---- experts: JOINT 2-token, W1/W2 on constant port ----
    const int rx0 = rowA * KSTR, rx1 = rowB * KSTR;
    const ull dnd0 = dup2(dn_[0]), snd0 = dup2(sn_[0]);
    const ull dnd1 = dup2(dn_[1]), snd1 = dup2(sn_[1]);
    ull moe0[8], moe1[8];
    {
        const ull *bg = (const ull*)w.b2g, *bs = (const ull*)w.b2s, *bf = (const ull*)w.b2f;
        const ull a0 = dup2(g_[0][0]), b0 = dup2(g_[0][1]), c0 = dup2(g_[0][2]);
        const ull a1 = dup2(g_[1][0]), b1 = dup2(g_[1][1]), c1 = dup2(g_[1][2]);
#pragma unroll
        for (int p = 0; p < 8; p++) {
            moe0[p] = fma2(a0, bg[p], fma2(b0, bs[p], fma2(c0, bf[p], 0ull)));
            moe1[p] = fma2(a1, bg[p], fma2(b1, bs[p], fma2(c1, bf[p], 0ull)));
        }
    }

#define EXPERT_C2(B1, B2, AA, BB, CC, E) {                                \
        ull h0[8], h1[8];                                                 \
        {                                                                 \
            const ull *Ap = (const ull*)(AA), *Bp = (const ull*)(BB),     \
                      *Cp = (const ull*)(CC);                             \
            _Pragma("unroll") for (int p = 0; p < 8; p++) {               \
                const ull Av = Ap[p], Bv = Bp[p], Cv = Cp[p];             \
                h0[p] = fma2(dnd0, Av, fma2(snd0, Bv, Cv));               \
                h1[p] = fma2(dnd1, Av, fma2(snd1, Bv, Cv));               \
            }                                                             \
        }                                                                 \
        _Pragma("unroll") for (int k = 0; k < 16; k++) {                  \
            const ull xv0 = dup2(s_x[rx0 + k]);                           \
            const ull xv1 = dup2(s_x[rx1 + k]);                           \
            _Pragma("unroll") for (int p = 0; p < 8; p++) {               \
                const ull wk = c_w64[(B1) + k*8 + p];                     \
                h0[p] = fma2(xv0, wk, h0[p]);                             \
                h1[p] = fma2(xv1, wk, h1[p]);                             \
            }                                                             \
        }                                                                 \
        float hf0[16], hf1[16];                                           \
        const float ge0 = g_[0][E], ge1 = g_[1][E];                       \
        _Pragma("unroll") for (int p = 0; p < 8; p++) {                   \
            float a0_, a1_;                                               \
            upk2(h0[p], a0_, a1_);                                        \
            hf0[2*p] = gelu_fast(a0_) * ge0; hf0[2*p+1] = gelu_fast(a1_) * ge0; \
            upk2(h1[p], a0_, a1_);                                        \
            hf1[2*p] = gelu_fast(a0_) * ge1; hf1[2*p+1] = gelu_fast(a1_) * ge1; \
        }                                                                 \
        _Pragma("unroll") for (int k = 0; k < 16; k++) {                  \
            const ull v0 = dup2(hf0[k]);                                  \
            const ull v1 = dup2(hf1[k]);                                  \
            _Pragma("unroll") for (int p = 0; p < 8; p++) {               \
                const ull wk = c_w64[(B2) + k*8 + p];                     \
                moe0[p] = fma2(v0, wk, moe0[p]);                          \
                moe1[p] = fma2(v1, wk, moe1[p]);                          \
            }                                                             \
        }                                                                 \
    }

    EXPERT_C2(CB_EG1, CB_EG2, w.Ag, w.Bg, w.Cg, 0)
    EXPERT_C2(CB_ES1, CB_ES2, w.As, w.Bs, w.Cs, 1)
    EXPERT_C2(CB_EF1, CB_EF2, w.Af, w.Bf, w.Cf, 2)
#undef EXPERT_C2

    // ---- final per token: residual folds + LN + project + sigmoid ----
#pragma unroll
    for (int tok = 0; tok < 2; tok++) {
        const int rx = tok ? rx1 : rx0;
        const ull* xr = (const ull*)&s_x[rx];
        const ull* mo = tok ? moe1 : moe0;
        const ull two = dup2(2.0f);
        const ull gdp = dup2(g_[tok][0] + g_[tok][2]);
        const ull gsp = dup2(g_[tok][1] + g_[tok][2]);
        const ull dnd = dup2(dn_[tok]), snd = dup2(sn_[tok]);
        const ull *dw = (const ull*)w.dpw, *db = (const ull*)w.dpb;
        const ull *sw = (const ull*)w.spw, *sb = (const ull*)w.spb;
        float mf[16];
#pragma unroll
        for (int p = 0; p < 8; p++) {
            ull v = fma2(two, xr[p], mo[p]);
            const ull dpf = fma2(dnd, dw[p], db[p]);
            const ull spf = fma2(snd, sw[p], sb[p]);
            v = fma2(gdp, dpf, v);
            v = fma2(gsp, spf, v);
            upk2(v, mf[2*p], mf[2*p+1]);
        }
        ln16(mf, w.n2g, w.n2b);
        const float* cpw = (const float*)&c_w64[CB_PW];
        float z = w.pb[0];
#pragma unroll
        for (int j = 0; j < 16; j++) z = fmaf(mf[j], cpw[j], z);
        out[pix_[tok]] = __fdividef(1.0f, 1.0f + __expf(-z));
    }

    __syncthreads();                                         // S6
    if (tid < 3) atomicAdd(&g_gate_acc[tid], s_gate[tid]);
}

__global__ void tail_kernel(float* __restrict__ out) {
    if (threadIdx.x < 3)
        out[NPIX + threadIdx.x] = (float)(g_gate_acc[threadIdx.x] / (double)NPATCH);
}

// ---------------- launch ----------------
extern "C" void kernel_launch(void* const* d_in, const int* in_sizes, int n_in,
                              void* d_out, int out_size) {
    Ptrs ptrs;
    for (int i = 0; i < 32; i++) ptrs.p[i] = (const float*)d_in[i];
    const float* depth = (const float*)d_in[0];
    const float* sem   = (const float*)d_in[1];
    float* out = (float*)d_out;

    cudaFuncSetAttribute(moe_kernel, cudaFuncAttributeMaxDynamicSharedMemorySize, SMEM_TOTAL);

    // populate constant weights from inputs (graph-capturable async D2D)
    void* caddr = nullptr;
    cudaGetSymbolAddress(&caddr, c_w64);
    cudaMemcpyAsync((char*)caddr + CB_EG1*8,  d_in[12], 1024, cudaMemcpyDeviceToDevice);
    cudaMemcpyAsync((char*)caddr + CB_EG2*8,  d_in[14], 1024, cudaMemcpyDeviceToDevice);
    cudaMemcpyAsync((char*)caddr + CB_ES1*8,  d_in[16], 1024, cudaMemcpyDeviceToDevice);
    cudaMemcpyAsync((char*)caddr + CB_ES2*8,  d_in[18], 1024, cudaMemcpyDeviceToDevice);
    cudaMemcpyAsync((char*)caddr + CB_EF1*8,  d_in[20], 1024, cudaMemcpyDeviceToDevice);
    cudaMemcpyAsync((char*)caddr + CB_EF2*8,  d_in[22], 1024, cudaMemcpyDeviceToDevice);
    cudaMemcpyAsync((char*)caddr + CB_GW2*8,  d_in[28], 192,  cudaMemcpyDeviceToDevice);
    cudaMemcpyAsync((char*)caddr + CB_PW*8,   d_in[30], 64,   cudaMemcpyDeviceToDevice);

    pack_kernel<<<1, 256>>>(ptrs);

    // wcx/xb0/Mh live at the head of g_wblob after pack_kernel phase 2.
    void* gaddr = nullptr;
    cudaGetSymbolAddress(&gaddr, g_wblob);
    cudaMemcpyAsync((char*)caddr + CB_WC0*8, gaddr, 576, cudaMemcpyDeviceToDevice);

    semprob_kernel<<<NPIX / 4 / 256, 256>>>(sem, depth);
    finalize_kernel<<<1, 32>>>();
    moe_kernel<<<NPATCH / PPB, TPB, SMEM_TOTAL>>>(depth, out);
    tail_kernel<<<1, 32>>>(out);
}